// round 7
// baseline (speedup 1.0000x reference)
#include <cuda_runtime.h>
#include <math.h>

#define BB   128
#define TT   256
#define HH   1024
#define KG   256     /* HH/4 feature-groups */
#define NBLK 256     /* 2 CTAs per SM */
#define NJ   4       /* output cols per CTA */
#define NTH  512
#define K4G  32      /* k4 steps per K-group (8 groups of 64 slots) */

typedef unsigned long long u64;

/* Scratch (static device globals; no runtime allocation). */
__device__ float4 g_pre0[(size_t)TT * KG * BB];   /* [t][j4][b] */
__device__ float4 g_h0buf[2][KG * BB];            /* layer-0 hidden, double buffered, [k4][b] */
__device__ float4 g_h1buf[2][KG * BB];            /* layer-1 hidden */
__device__ unsigned int g_cnt;                    /* grid barrier counter */

/* ---------------- packed fp32x2 helpers (FFMA2 path) ---------------- */
__device__ __forceinline__ u64 fma2(u64 a, u64 b, u64 c) {
    u64 d; asm("fma.rn.f32x2 %0, %1, %2, %3;" : "=l"(d) : "l"(a), "l"(b), "l"(c)); return d;
}
__device__ __forceinline__ u64 pack2(float x, float y) {
    u64 r; asm("mov.b64 %0, {%1, %2};" : "=l"(r) : "f"(x), "f"(y)); return r;
}
__device__ __forceinline__ float2 unpk(u64 v) {
    float2 f; asm("mov.b64 {%0, %1}, %2;" : "=f"(f.x), "=f"(f.y) : "l"(v)); return f;
}
__device__ __forceinline__ void ldcg2(const float4* p, u64& x, u64& y) {
    asm("ld.global.cg.v2.u64 {%0,%1}, [%2];" : "=l"(x), "=l"(y) : "l"(p));
}

/* ------------------------------------------------------------------ */
/* Kernel 1: pre0[t][j][b] = sum_k x[b][t][k]*Wi0[k][j] + bi0[j]       */
/* ------------------------------------------------------------------ */
__global__ __launch_bounds__(256) void pre_gemm(const float* __restrict__ x,
                                                const float* __restrict__ Wi,
                                                const float* __restrict__ bi)
{
    if (blockIdx.x == 0 && blockIdx.y == 0 && threadIdx.x == 0) g_cnt = 0u;

    __shared__ float  sA[32][129];
    __shared__ float4 sB[32 * 16];

    const int t     = blockIdx.y;
    const int jbase = blockIdx.x * 64;
    const int tid   = threadIdx.x;
    const int rid   = tid & 31;
    const int cid   = tid >> 5;

    u64 acc[4][4];
#pragma unroll
    for (int i = 0; i < 4; ++i)
#pragma unroll
        for (int j = 0; j < 4; ++j) acc[i][j] = 0ull;

    const int brow = tid >> 1;
    const int half = tid & 1;

    for (int k0 = 0; k0 < HH; k0 += 32) {
        __syncthreads();
        const float* xs = x + ((size_t)brow * TT + t) * HH + k0 + half * 16;
#pragma unroll
        for (int q = 0; q < 4; ++q) {
            float4 v = *(const float4*)(xs + 4 * q);
            int kk = half * 16 + 4 * q;
            sA[kk + 0][brow] = v.x; sA[kk + 1][brow] = v.y;
            sA[kk + 2][brow] = v.z; sA[kk + 3][brow] = v.w;
        }
#pragma unroll
        for (int q = 0; q < 2; ++q) {
            int idx = tid + 256 * q;
            int kk = idx >> 4, jf = idx & 15;
            sB[idx] = *(const float4*)(Wi + (size_t)(k0 + kk) * HH + jbase + 4 * jf);
        }
        __syncthreads();

#pragma unroll
        for (int kk = 0; kk < 32; ++kk) {
            float a0 = sA[kk][rid], a1 = sA[kk][rid + 32];
            float a2 = sA[kk][rid + 64], a3 = sA[kk][rid + 96];
            const ulonglong2* bp = (const ulonglong2*)&sB[kk * 16 + cid * 2];
            ulonglong2 bb0 = bp[0];
            ulonglong2 bb1 = bp[1];
            u64 ad0 = pack2(a0, a0), ad1 = pack2(a1, a1);
            u64 ad2 = pack2(a2, a2), ad3 = pack2(a3, a3);
            acc[0][0] = fma2(ad0, bb0.x, acc[0][0]); acc[0][1] = fma2(ad0, bb0.y, acc[0][1]);
            acc[0][2] = fma2(ad0, bb1.x, acc[0][2]); acc[0][3] = fma2(ad0, bb1.y, acc[0][3]);
            acc[1][0] = fma2(ad1, bb0.x, acc[1][0]); acc[1][1] = fma2(ad1, bb0.y, acc[1][1]);
            acc[1][2] = fma2(ad1, bb1.x, acc[1][2]); acc[1][3] = fma2(ad1, bb1.y, acc[1][3]);
            acc[2][0] = fma2(ad2, bb0.x, acc[2][0]); acc[2][1] = fma2(ad2, bb0.y, acc[2][1]);
            acc[2][2] = fma2(ad2, bb1.x, acc[2][2]); acc[2][3] = fma2(ad2, bb1.y, acc[2][3]);
            acc[3][0] = fma2(ad3, bb0.x, acc[3][0]); acc[3][1] = fma2(ad3, bb0.y, acc[3][1]);
            acc[3][2] = fma2(ad3, bb1.x, acc[3][2]); acc[3][3] = fma2(ad3, bb1.y, acc[3][3]);
        }
    }

    float biv[8];
#pragma unroll
    for (int j = 0; j < 8; ++j) biv[j] = __ldg(&bi[jbase + cid * 8 + j]);

    const int jg = (jbase + cid * 8) >> 2;
#pragma unroll
    for (int i = 0; i < 4; ++i) {
        int row = rid + 32 * i;
#pragma unroll
        for (int gq = 0; gq < 2; ++gq) {
            float2 u0 = unpk(acc[i][2 * gq]);
            float2 u1 = unpk(acc[i][2 * gq + 1]);
            float4 v;
            v.x = u0.x + biv[4 * gq + 0];
            v.y = u0.y + biv[4 * gq + 1];
            v.z = u1.x + biv[4 * gq + 2];
            v.w = u1.y + biv[4 * gq + 3];
            g_pre0[((size_t)t * KG + jg + gq) * BB + row] = v;
        }
    }
}

/* ------------------------------------------------------------------ */
__device__ __forceinline__ void grid_sync(unsigned int target)
{
    __syncthreads();
    if (threadIdx.x == 0) {
        __threadfence();
        atomicAdd(&g_cnt, 1u);
        while (*(volatile unsigned int*)&g_cnt < target) { }
        __threadfence();
    }
    __syncthreads();
}

/* sred: [16 i][8 g][65 slot]; i = jj + 4*rowhalf + 8*accsel */
#define RIDX(i, g, s) ((((i) * 8 + (g)) * 65) + (s))

/* jj bodies: loop1 feeds acc1 (Wi1) + acc0 (Wh0) from A0; loop2 feeds acc1 (Wh1) from A1 */
#define JJ1(cax, cay, cbx, cby, OFF)                                              \
    {                                                                             \
        int off_ = (OFF);                                                         \
        _Pragma("unroll")                                                         \
        for (int jj = 0; jj < NJ; ++jj) {                                         \
            ulonglong2 w1 = *(const ulonglong2*)&sWi1[jj * 256 + off_];           \
            acc1r0[jj] = fma2(cax, w1.x, fma2(cay, w1.y, acc1r0[jj]));            \
            acc1r1[jj] = fma2(cbx, w1.x, fma2(cby, w1.y, acc1r1[jj]));            \
            ulonglong2 w0 = *(const ulonglong2*)&sWh0[jj * 256 + off_];           \
            acc0r0[jj] = fma2(cax, w0.x, fma2(cay, w0.y, acc0r0[jj]));            \
            acc0r1[jj] = fma2(cbx, w0.x, fma2(cby, w0.y, acc0r1[jj]));            \
        }                                                                         \
    }

#define JJ2(cax, cay, cbx, cby, OFF)                                              \
    {                                                                             \
        int off_ = (OFF);                                                         \
        _Pragma("unroll")                                                         \
        for (int jj = 0; jj < NJ; ++jj) {                                         \
            ulonglong2 w = *(const ulonglong2*)&sWh1[jj * 256 + off_];            \
            acc1r0[jj] = fma2(cax, w.x, fma2(cay, w.y, acc1r0[jj]));              \
            acc1r1[jj] = fma2(cbx, w.x, fma2(cby, w.y, acc1r1[jj]));              \
        }                                                                         \
    }

/* ------------------------------------------------------------------ */
/* Kernel 2: persistent RNN, FFMA2, 256 CTAs (2/SM), 512 threads.      */
/* CTA owns NJ=4 output cols. thread = (K-group g of 8, row-slot 64).  */
/* __launch_bounds__(512,2) pins regs<=64 -> 2-CTA residency is        */
/* guaranteed, so the 256-CTA grid barrier cannot deadlock.            */
/* ------------------------------------------------------------------ */
__global__ __launch_bounds__(NTH, 2) void rnn_persist(const float* __restrict__ h0,
                                                      const float* __restrict__ Wi,
                                                      const float* __restrict__ bi,
                                                      const float* __restrict__ Wh,
                                                      const float* __restrict__ bh,
                                                      float* __restrict__ out)
{
    extern __shared__ float4 smem4[];
    float4* sWh0 = smem4;              /* [4 cols][256 k4] */
    float4* sWi1 = smem4 + 1024;
    float4* sWh1 = smem4 + 2048;
    float*  sred = (float*)(smem4 + 3072);          /* [16][8][65] partials */
    float*  sdot = sred + 16 * 8 * 65;              /* [8][4] init dot */

    const int cta  = blockIdx.x;
    const int th   = threadIdx.x;
    const int g    = th >> 6;          /* K group 0..7 */
    const int slot = th & 63;          /* row slot: rows slot, slot+64 */
    const int j0   = cta * NJ;

    /* final-pass mapping (all 512 threads): 1 (row,col) each */
    const int frow = th >> 2;          /* 0..127 */
    const int col  = th & 3;           /* CTA col 0..3 */
    const int fslot = frow & 63;
    const int frh   = frow >> 6;

    const float* Wi1g = Wi + (size_t)HH * HH;
    const float* Wh1g = Wh + (size_t)HH * HH;

    /* One-time: gather weight column slices into SMEM (float4 over k). */
    for (int idx = th; idx < 1024; idx += NTH) {
        int jl = idx >> 8, k4 = idx & 255;
        int j = j0 + jl;
        int kb = k4 * 4;
        sWh0[idx] = make_float4(Wh[(size_t)(kb + 0) * HH + j], Wh[(size_t)(kb + 1) * HH + j],
                                Wh[(size_t)(kb + 2) * HH + j], Wh[(size_t)(kb + 3) * HH + j]);
        sWi1[idx] = make_float4(Wi1g[(size_t)(kb + 0) * HH + j], Wi1g[(size_t)(kb + 1) * HH + j],
                                Wi1g[(size_t)(kb + 2) * HH + j], Wi1g[(size_t)(kb + 3) * HH + j]);
        sWh1[idx] = make_float4(Wh1g[(size_t)(kb + 0) * HH + j], Wh1g[(size_t)(kb + 1) * HH + j],
                                Wh1g[(size_t)(kb + 2) * HH + j], Wh1g[(size_t)(kb + 3) * HH + j]);
    }

    const float bs1 = __ldg(&bi[HH + j0 + col]) + __ldg(&bh[HH + j0 + col]);
    const float b0r = __ldg(&bh[j0 + col]);

    /* h1 init: CTA cta covers k4 = cta (256 CTAs x 1 k4). */
    if (th < BB) {
        g_h1buf[1][cta * BB + th] = *(const float4*)(h0 + HH + 4 * cta);
    }
    __syncthreads();

    /* hn0[0] init: dot0[col] = h0_l0 @ Wh0 (shared over batch rows). */
    {
        u64 d[NJ];
#pragma unroll
        for (int jj = 0; jj < NJ; ++jj) d[jj] = 0ull;
        for (int kk = 0; kk < K4G; ++kk) {
            int off = g * K4G + kk;
            ulonglong2 a = *(const ulonglong2*)(h0 + 4 * off);
#pragma unroll
            for (int jj = 0; jj < NJ; ++jj) {
                ulonglong2 w = *(const ulonglong2*)&sWh0[jj * 256 + off];
                d[jj] = fma2(a.x, w.x, fma2(a.y, w.y, d[jj]));
            }
        }
        if (slot == 0) {
#pragma unroll
            for (int jj = 0; jj < NJ; ++jj) {
                float2 f = unpk(d[jj]);
                sdot[g * NJ + jj] = f.x + f.y;
            }
        }
        __syncthreads();
        float dv = 0.0f;
#pragma unroll
        for (int g2 = 0; g2 < 8; ++g2) dv += sdot[g2 * NJ + col];
        float pre = ((const float*)g_pre0)[((size_t)cta * BB + frow) * 4 + col];
        ((float*)g_h0buf[0])[((size_t)cta * BB + frow) * 4 + col] = tanhf(pre + dv + b0r);
    }

    unsigned int ph = 1;
    grid_sync(ph * NBLK); ++ph;

    for (int t = 0; t < TT; ++t) {
        const float4* p0 = g_h0buf[t & 1]       + (size_t)g * K4G * BB + slot;
        const float4* p1 = g_h1buf[(t + 1) & 1] + (size_t)g * K4G * BB + slot;

        /* Hoisted prefetch: next-step pre0 (1 scalar). */
        float pn = 0.0f;
        if (t < TT - 1) {
            pn = __ldcg(&((const float*)g_pre0)[((size_t)((size_t)(t + 1) * KG + cta) * BB + frow) * 4 + col]);
        }

        u64 acc1r0[NJ], acc1r1[NJ], acc0r0[NJ], acc0r1[NJ];
#pragma unroll
        for (int jj = 0; jj < NJ; ++jj) {
            acc1r0[jj] = 0ull; acc1r1[jj] = 0ull;
            acc0r0[jj] = 0ull; acc0r1[jj] = 0ull;
        }

        /* Loop 1: A0 feeds Wi1 (acc1) and Wh0 (acc0). Depth-2 prefetch. */
        {
            u64 A0x, A0y, B0x, B0y, A1x, A1y, B1x, B1y;
            ldcg2(p0,          A0x, A0y); ldcg2(p0 + 64,      B0x, B0y);
            ldcg2(p0 + BB,     A1x, A1y); ldcg2(p0 + BB + 64, B1x, B1y);
#pragma unroll 1
            for (int kk = 0; kk < K4G; kk += 2) {
                int off = g * K4G + kk;
                JJ1(A0x, A0y, B0x, B0y, off);
                if (kk + 2 < K4G) {
                    ldcg2(p0 + (kk + 2) * BB,      A0x, A0y);
                    ldcg2(p0 + (kk + 2) * BB + 64, B0x, B0y);
                }
                JJ1(A1x, A1y, B1x, B1y, off + 1);
                if (kk + 3 < K4G) {
                    ldcg2(p0 + (kk + 3) * BB,      A1x, A1y);
                    ldcg2(p0 + (kk + 3) * BB + 64, B1x, B1y);
                }
            }
        }
        /* Loop 2: A1 feeds Wh1 (acc1). Depth-2 prefetch. */
        {
            u64 A0x, A0y, B0x, B0y, A1x, A1y, B1x, B1y;
            ldcg2(p1,          A0x, A0y); ldcg2(p1 + 64,      B0x, B0y);
            ldcg2(p1 + BB,     A1x, A1y); ldcg2(p1 + BB + 64, B1x, B1y);
#pragma unroll 1
            for (int kk = 0; kk < K4G; kk += 2) {
                int off = g * K4G + kk;
                JJ2(A0x, A0y, B0x, B0y, off);
                if (kk + 2 < K4G) {
                    ldcg2(p1 + (kk + 2) * BB,      A0x, A0y);
                    ldcg2(p1 + (kk + 2) * BB + 64, B0x, B0y);
                }
                JJ2(A1x, A1y, B1x, B1y, off + 1);
                if (kk + 3 < K4G) {
                    ldcg2(p1 + (kk + 3) * BB,      A1x, A1y);
                    ldcg2(p1 + (kk + 3) * BB + 64, B1x, B1y);
                }
            }
        }

        /* Collapse (lo+hi) and write partials for 8-way K reduction. */
#pragma unroll
        for (int jj = 0; jj < NJ; ++jj) {
            float2 v;
            v = unpk(acc1r0[jj]); sred[RIDX(jj,          g, slot)] = v.x + v.y;
            v = unpk(acc1r1[jj]); sred[RIDX(jj + 4,      g, slot)] = v.x + v.y;
            v = unpk(acc0r0[jj]); sred[RIDX(jj + 8,      g, slot)] = v.x + v.y;
            v = unpk(acc0r1[jj]); sred[RIDX(jj + 12,     g, slot)] = v.x + v.y;
        }
        __syncthreads();

        /* Final pass: 512 threads, 1 (row,col) each: acc1 sum + acc0 sum. */
        {
            float s1 = 0.0f;
#pragma unroll
            for (int g2 = 0; g2 < 8; ++g2) s1 += sred[RIDX(col + 4 * frh, g2, fslot)];
            float y = tanhf(s1 + bs1);
            out[((size_t)frow * TT + t) * HH + j0 + col] = y;
            ((float*)g_h1buf[t & 1])[((size_t)cta * BB + frow) * 4 + col] = y;

            if (t < TT - 1) {
                float s0 = 0.0f;
#pragma unroll
                for (int g2 = 0; g2 < 8; ++g2) s0 += sred[RIDX(col + 4 * frh + 8, g2, fslot)];
                ((float*)g_h0buf[(t + 1) & 1])[((size_t)cta * BB + frow) * 4 + col] =
                    tanhf(s0 + pn + b0r);
            } else {
                float* hn = out + (size_t)BB * TT * HH;
                hn[(size_t)(frow * 2 + 1) * HH + j0 + col] = y;
                float l0 = __ldcg(&((const float*)g_h0buf[t & 1])[((size_t)cta * BB + frow) * 4 + col]);
                hn[(size_t)(frow * 2) * HH + j0 + col] = l0;
            }
        }

        if (t < TT - 1) { grid_sync(ph * NBLK); ++ph; }
    }
}

/* ------------------------------------------------------------------ */
extern "C" void kernel_launch(void* const* d_in, const int* in_sizes, int n_in,
                              void* d_out, int out_size)
{
    const float* x  = (const float*)d_in[0];
    const float* h0 = (const float*)d_in[1];
    const float* Wi = (const float*)d_in[2];
    const float* bi = (const float*)d_in[3];
    const float* Wh = (const float*)d_in[4];
    const float* bh = (const float*)d_in[5];
    float* out = (float*)d_out;

    dim3 g2(16, 256);
    pre_gemm<<<g2, 256>>>(x, Wi, bi);

    size_t smem = 3072 * sizeof(float4) + (16 * 8 * 65 + 32) * sizeof(float);  /* ~81.6 KB */
    cudaFuncSetAttribute(rnn_persist, cudaFuncAttributeMaxDynamicSharedMemorySize, (int)smem);
    rnn_persist<<<NBLK, NTH, smem>>>(h0, Wi, bi, Wh, bh, out);
}

// round 8
// speedup vs baseline: 1.2066x; 1.2066x over previous
#include <cuda_runtime.h>
#include <math.h>

#define BB   128
#define TT   256
#define HH   1024
#define KG   256     /* HH/4 feature-groups */
#define NBLK 128
#define NJ   8       /* output cols per CTA */
#define NTH  512
#define K4G  32      /* k4 steps per K-group (8 groups of 64 slots) */

typedef unsigned long long u64;

/* Scratch (static device globals; no runtime allocation). */
__device__ float4 g_pre0[(size_t)TT * KG * BB];   /* [t][j4][b] */
__device__ float4 g_h0buf[2][KG * BB];            /* layer-0 hidden, double buffered, [k4][b] */
__device__ float4 g_h1buf[2][KG * BB];            /* layer-1 hidden */
__device__ unsigned int g_cnt;                    /* grid barrier counter */

/* ---------------- packed fp32x2 helpers (FFMA2 path) ---------------- */
__device__ __forceinline__ u64 fma2(u64 a, u64 b, u64 c) {
    u64 d; asm("fma.rn.f32x2 %0, %1, %2, %3;" : "=l"(d) : "l"(a), "l"(b), "l"(c)); return d;
}
__device__ __forceinline__ u64 pack2(float x, float y) {
    u64 r; asm("mov.b64 %0, {%1, %2};" : "=l"(r) : "f"(x), "f"(y)); return r;
}
__device__ __forceinline__ float2 unpk(u64 v) {
    float2 f; asm("mov.b64 {%0, %1}, %2;" : "=f"(f.x), "=f"(f.y) : "l"(v)); return f;
}
__device__ __forceinline__ void ldcg2(const float4* p, u64& x, u64& y) {
    asm("ld.global.cg.v2.u64 {%0,%1}, [%2];" : "=l"(x), "=l"(y) : "l"(p));
}

/* ------------------------------------------------------------------ */
/* Kernel 1: pre0[t][j][b] = sum_k x[b][t][k]*Wi0[k][j] + bi0[j]       */
/* ------------------------------------------------------------------ */
__global__ __launch_bounds__(256) void pre_gemm(const float* __restrict__ x,
                                                const float* __restrict__ Wi,
                                                const float* __restrict__ bi)
{
    if (blockIdx.x == 0 && blockIdx.y == 0 && threadIdx.x == 0) g_cnt = 0u;

    __shared__ float  sA[32][129];
    __shared__ float4 sB[32 * 16];

    const int t     = blockIdx.y;
    const int jbase = blockIdx.x * 64;
    const int tid   = threadIdx.x;
    const int rid   = tid & 31;
    const int cid   = tid >> 5;

    u64 acc[4][4];
#pragma unroll
    for (int i = 0; i < 4; ++i)
#pragma unroll
        for (int j = 0; j < 4; ++j) acc[i][j] = 0ull;

    const int brow = tid >> 1;
    const int half = tid & 1;

    for (int k0 = 0; k0 < HH; k0 += 32) {
        __syncthreads();
        const float* xs = x + ((size_t)brow * TT + t) * HH + k0 + half * 16;
#pragma unroll
        for (int q = 0; q < 4; ++q) {
            float4 v = *(const float4*)(xs + 4 * q);
            int kk = half * 16 + 4 * q;
            sA[kk + 0][brow] = v.x; sA[kk + 1][brow] = v.y;
            sA[kk + 2][brow] = v.z; sA[kk + 3][brow] = v.w;
        }
#pragma unroll
        for (int q = 0; q < 2; ++q) {
            int idx = tid + 256 * q;
            int kk = idx >> 4, jf = idx & 15;
            sB[idx] = *(const float4*)(Wi + (size_t)(k0 + kk) * HH + jbase + 4 * jf);
        }
        __syncthreads();

#pragma unroll
        for (int kk = 0; kk < 32; ++kk) {
            float a0 = sA[kk][rid], a1 = sA[kk][rid + 32];
            float a2 = sA[kk][rid + 64], a3 = sA[kk][rid + 96];
            const ulonglong2* bp = (const ulonglong2*)&sB[kk * 16 + cid * 2];
            ulonglong2 bb0 = bp[0];
            ulonglong2 bb1 = bp[1];
            u64 ad0 = pack2(a0, a0), ad1 = pack2(a1, a1);
            u64 ad2 = pack2(a2, a2), ad3 = pack2(a3, a3);
            acc[0][0] = fma2(ad0, bb0.x, acc[0][0]); acc[0][1] = fma2(ad0, bb0.y, acc[0][1]);
            acc[0][2] = fma2(ad0, bb1.x, acc[0][2]); acc[0][3] = fma2(ad0, bb1.y, acc[0][3]);
            acc[1][0] = fma2(ad1, bb0.x, acc[1][0]); acc[1][1] = fma2(ad1, bb0.y, acc[1][1]);
            acc[1][2] = fma2(ad1, bb1.x, acc[1][2]); acc[1][3] = fma2(ad1, bb1.y, acc[1][3]);
            acc[2][0] = fma2(ad2, bb0.x, acc[2][0]); acc[2][1] = fma2(ad2, bb0.y, acc[2][1]);
            acc[2][2] = fma2(ad2, bb1.x, acc[2][2]); acc[2][3] = fma2(ad2, bb1.y, acc[2][3]);
            acc[3][0] = fma2(ad3, bb0.x, acc[3][0]); acc[3][1] = fma2(ad3, bb0.y, acc[3][1]);
            acc[3][2] = fma2(ad3, bb1.x, acc[3][2]); acc[3][3] = fma2(ad3, bb1.y, acc[3][3]);
        }
    }

    float biv[8];
#pragma unroll
    for (int j = 0; j < 8; ++j) biv[j] = __ldg(&bi[jbase + cid * 8 + j]);

    const int jg = (jbase + cid * 8) >> 2;
#pragma unroll
    for (int i = 0; i < 4; ++i) {
        int row = rid + 32 * i;
#pragma unroll
        for (int gq = 0; gq < 2; ++gq) {
            float2 u0 = unpk(acc[i][2 * gq]);
            float2 u1 = unpk(acc[i][2 * gq + 1]);
            float4 v;
            v.x = u0.x + biv[4 * gq + 0];
            v.y = u0.y + biv[4 * gq + 1];
            v.z = u1.x + biv[4 * gq + 2];
            v.w = u1.y + biv[4 * gq + 3];
            g_pre0[((size_t)t * KG + jg + gq) * BB + row] = v;
        }
    }
}

/* ------------------------------------------------------------------ */
__device__ __forceinline__ void grid_sync(unsigned int target)
{
    __syncthreads();
    if (threadIdx.x == 0) {
        __threadfence();
        atomicAdd(&g_cnt, 1u);
        while (*(volatile unsigned int*)&g_cnt < target) { }
        __threadfence();
    }
    __syncthreads();
}

#define RIDX(i, g, s) ((((i) * 8 + (g)) * 65) + (s))

/* Weights interleaved at power-of-2 stride: sWall[k4*32 + m], m = 0..7 Wi1,
   8..15 Wh1, 16..23 Wh0, 24..31 pad. Per-kk: one pointer bump, 24 LDS at
   immediate offsets.                                                        */

/* Load A pair for loop1/loop2 step KK into stage S regs. */
#define LD1(S, KK)  ldcg2(p0 + (KK) * BB, A##S##x, A##S##y); \
                    ldcg2(p0 + (KK) * BB + 64, B##S##x, B##S##y);
#define LD2(S, KK)  ldcg2(p1 + (KK) * BB, A##S##x, A##S##y); \
                    ldcg2(p1 + (KK) * BB + 64, B##S##x, B##S##y);

/* Body 1: 8 jj x {Wi1 -> acc1, Wh0 -> acc0} from stage S at step KK. */
#define JJ1(S, KK)                                                                \
    {                                                                             \
        const ulonglong2* wk_ = (const ulonglong2*)(wbase + ((KK) << 5));         \
        _Pragma("unroll")                                                         \
        for (int jj = 0; jj < NJ; ++jj) {                                         \
            ulonglong2 w1 = wk_[jj];                                              \
            acc1r0[jj] = fma2(A##S##x, w1.x, fma2(A##S##y, w1.y, acc1r0[jj]));    \
            acc1r1[jj] = fma2(B##S##x, w1.x, fma2(B##S##y, w1.y, acc1r1[jj]));    \
            ulonglong2 w0 = wk_[16 + jj];                                         \
            acc0r0[jj] = fma2(A##S##x, w0.x, fma2(A##S##y, w0.y, acc0r0[jj]));    \
            acc0r1[jj] = fma2(B##S##x, w0.x, fma2(B##S##y, w0.y, acc0r1[jj]));    \
        }                                                                         \
    }

/* Body 2: 8 jj x {Wh1 -> acc1} from stage S at step KK. */
#define JJ2(S, KK)                                                                \
    {                                                                             \
        const ulonglong2* wk_ = (const ulonglong2*)(wbase + ((KK) << 5));         \
        _Pragma("unroll")                                                         \
        for (int jj = 0; jj < NJ; ++jj) {                                         \
            ulonglong2 w = wk_[8 + jj];                                           \
            acc1r0[jj] = fma2(A##S##x, w.x, fma2(A##S##y, w.y, acc1r0[jj]));      \
            acc1r1[jj] = fma2(B##S##x, w.x, fma2(B##S##y, w.y, acc1r1[jj]));      \
        }                                                                         \
    }

/* ------------------------------------------------------------------ */
/* Kernel 2: persistent weight-stationary RNN, FFMA2, 512 threads.     */
/* thread = (K-group g of 8, row-slot of 64); rows slot and slot+64.   */
/* 4-deep LDG pipeline, pow2-interleaved weights (imm-offset LDS).     */
/* ------------------------------------------------------------------ */
__global__ __launch_bounds__(NTH, 1) void rnn_persist(const float* __restrict__ h0,
                                                      const float* __restrict__ Wi,
                                                      const float* __restrict__ bi,
                                                      const float* __restrict__ Wh,
                                                      const float* __restrict__ bh,
                                                      float* __restrict__ out)
{
    extern __shared__ float4 smem4[];
    float4* sWall = smem4;                          /* [256 k4][32] interleaved */
    float*  sred = (float*)(smem4 + 8192);          /* [32][8][65] partials */
    float*  sdot = sred + 32 * 8 * 65;              /* [8][8] init dot */

    const int cta  = blockIdx.x;
    const int th   = threadIdx.x;
    const int g    = th >> 6;          /* K group 0..7 */
    const int slot = th & 63;          /* row slot: rows slot, slot+64 */
    const int j0   = cta * NJ;

    /* final-pass mapping (all 512 threads): */
    const int frow = th >> 2;          /* 0..127 */
    const int c0   = (th & 3) * 2;     /* cols c0, c0+1 of this CTA's 8 */
    const int fslot = frow & 63;
    const int frh   = frow >> 6;
    const int fjg4  = (j0 + c0) >> 2;
    const int fcl   = c0 & 3;

    const float* Wi1g = Wi + (size_t)HH * HH;
    const float* Wh1g = Wh + (size_t)HH * HH;

    /* One-time: interleaved weight gather. m: 0-7 Wi1, 8-15 Wh1, 16-23 Wh0. */
    for (int idx = th; idx < 8192; idx += NTH) {
        int k4 = idx >> 5, m = idx & 31;
        if (m >= 24) continue;
        int j  = j0 + (m & 7);
        int kb = k4 * 4;
        const float* M = (m < 8) ? Wi1g : (m < 16) ? Wh1g : Wh;
        sWall[idx] = make_float4(M[(size_t)(kb + 0) * HH + j], M[(size_t)(kb + 1) * HH + j],
                                 M[(size_t)(kb + 2) * HH + j], M[(size_t)(kb + 3) * HH + j]);
    }

    float bs1[2], b0r[2];
#pragma unroll
    for (int e = 0; e < 2; ++e) {
        bs1[e] = __ldg(&bi[HH + j0 + c0 + e]) + __ldg(&bh[HH + j0 + c0 + e]);
        b0r[e] = __ldg(&bh[j0 + c0 + e]);
    }

    /* h1 init: CTA covers k4 in [2*cta, 2*cta+2), broadcast h0 layer 1. */
    for (int idx = th; idx < 2 * BB; idx += NTH) {
        int k4l = idx >> 7, b = idx & 127;
        g_h1buf[1][(2 * cta + k4l) * BB + b] = *(const float4*)(h0 + HH + 4 * (2 * cta + k4l));
    }
    __syncthreads();

    /* hn0[0] init: dot0[col] = h0_l0 @ Wh0 (shared over batch rows). */
    {
        u64 d[NJ];
#pragma unroll
        for (int jj = 0; jj < NJ; ++jj) d[jj] = 0ull;
        for (int kk = 0; kk < K4G; ++kk) {
            int off = g * K4G + kk;
            ulonglong2 a = *(const ulonglong2*)(h0 + 4 * off);
#pragma unroll
            for (int jj = 0; jj < NJ; ++jj) {
                ulonglong2 w = *(const ulonglong2*)&sWall[(off << 5) + 16 + jj];
                d[jj] = fma2(a.x, w.x, fma2(a.y, w.y, d[jj]));
            }
        }
        if (slot == 0) {
#pragma unroll
            for (int jj = 0; jj < NJ; ++jj) {
                float2 f = unpk(d[jj]);
                sdot[g * 8 + jj] = f.x + f.y;
            }
        }
        __syncthreads();
        const float* preF = (const float*)g_pre0;
#pragma unroll
        for (int e = 0; e < 2; ++e) {
            int col = c0 + e;
            float dv = 0.0f;
#pragma unroll
            for (int g2 = 0; g2 < 8; ++g2) dv += sdot[g2 * 8 + col];
            int jg4 = (j0 + col) >> 2;
            float pre = preF[((size_t)jg4 * BB + frow) * 4 + (col & 3)];
            ((float*)g_h0buf[0])[((size_t)jg4 * BB + frow) * 4 + (col & 3)] = tanhf(pre + dv + b0r[e]);
        }
    }

    unsigned int ph = 1;
    grid_sync(ph * NBLK); ++ph;

    const float4* wbase = sWall + ((size_t)g * K4G << 5);

    for (int t = 0; t < TT; ++t) {
        const float4* p0 = g_h0buf[t & 1]       + (size_t)g * K4G * BB + slot;
        const float4* p1 = g_h1buf[(t + 1) & 1] + (size_t)g * K4G * BB + slot;

        /* Hoisted prefetch: next-step pre0 (cols c0, c0+1 adjacent). */
        float2 pn = make_float2(0.0f, 0.0f);
        if (t < TT - 1) {
            const float* pp = (const float*)g_pre0 +
                ((size_t)((size_t)(t + 1) * KG + fjg4) * BB + frow) * 4 + fcl;
            asm("ld.global.cg.v2.f32 {%0,%1}, [%2];" : "=f"(pn.x), "=f"(pn.y) : "l"(pp));
        }

        u64 acc1r0[NJ], acc1r1[NJ], acc0r0[NJ], acc0r1[NJ];
#pragma unroll
        for (int jj = 0; jj < NJ; ++jj) {
            acc1r0[jj] = 0ull; acc1r1[jj] = 0ull;
            acc0r0[jj] = 0ull; acc0r1[jj] = 0ull;
        }

        /* Loop 1: A0 feeds Wi1 (acc1) and Wh0 (acc0). 4-deep pipeline. */
        {
            u64 A0x, A0y, B0x, B0y, A1x, A1y, B1x, B1y;
            u64 A2x, A2y, B2x, B2y, A3x, A3y, B3x, B3y;
            LD1(0, 0); LD1(1, 1); LD1(2, 2); LD1(3, 3);
#pragma unroll 1
            for (int kk = 0; kk < K4G; kk += 4) {
                JJ1(0, kk);     if (kk + 4 < K4G) { LD1(0, kk + 4); }
                JJ1(1, kk + 1); if (kk + 5 < K4G) { LD1(1, kk + 5); }
                JJ1(2, kk + 2); if (kk + 6 < K4G) { LD1(2, kk + 6); }
                JJ1(3, kk + 3); if (kk + 7 < K4G) { LD1(3, kk + 7); }
            }
        }
        /* Loop 2: A1 feeds Wh1 (acc1). 4-deep pipeline. */
        {
            u64 A0x, A0y, B0x, B0y, A1x, A1y, B1x, B1y;
            u64 A2x, A2y, B2x, B2y, A3x, A3y, B3x, B3y;
            LD2(0, 0); LD2(1, 1); LD2(2, 2); LD2(3, 3);
#pragma unroll 1
            for (int kk = 0; kk < K4G; kk += 4) {
                JJ2(0, kk);     if (kk + 4 < K4G) { LD2(0, kk + 4); }
                JJ2(1, kk + 1); if (kk + 5 < K4G) { LD2(1, kk + 5); }
                JJ2(2, kk + 2); if (kk + 6 < K4G) { LD2(2, kk + 6); }
                JJ2(3, kk + 3); if (kk + 7 < K4G) { LD2(3, kk + 7); }
            }
        }

        /* Collapse (lo+hi) and write partials for 8-way K reduction. */
#pragma unroll
        for (int jj = 0; jj < NJ; ++jj) {
            float2 v;
            v = unpk(acc1r0[jj]); sred[RIDX(jj,      g, slot)] = v.x + v.y;
            v = unpk(acc1r1[jj]); sred[RIDX(jj + 8,  g, slot)] = v.x + v.y;
            v = unpk(acc0r0[jj]); sred[RIDX(jj + 16, g, slot)] = v.x + v.y;
            v = unpk(acc0r1[jj]); sred[RIDX(jj + 24, g, slot)] = v.x + v.y;
        }
        __syncthreads();

        /* Final pass: all 512 threads, 2 (row,col) scalars each. */
        {
            float* h1w = (float*)g_h1buf[t & 1];
#pragma unroll
            for (int e = 0; e < 2; ++e) {
                int col = c0 + e;
                float s1 = 0.0f;
#pragma unroll
                for (int g2 = 0; g2 < 8; ++g2) s1 += sred[RIDX(col + 8 * frh, g2, fslot)];
                float y = tanhf(s1 + bs1[e]);
                int jg4 = (j0 + col) >> 2;
                out[((size_t)frow * TT + t) * HH + j0 + col] = y;
                h1w[((size_t)jg4 * BB + frow) * 4 + (col & 3)] = y;

                if (t < TT - 1) {
                    float s0 = 0.0f;
#pragma unroll
                    for (int g2 = 0; g2 < 8; ++g2) s0 += sred[RIDX(col + 8 * (2 + frh), g2, fslot)];
                    float pre = (e == 0) ? pn.x : pn.y;
                    ((float*)g_h0buf[(t + 1) & 1])[((size_t)jg4 * BB + frow) * 4 + (col & 3)] =
                        tanhf(s0 + pre + b0r[e]);
                } else {
                    float* hn = out + (size_t)BB * TT * HH;
                    hn[(size_t)(frow * 2 + 1) * HH + j0 + col] = y;
                    float l0 = __ldcg(&((const float*)g_h0buf[t & 1])[((size_t)jg4 * BB + frow) * 4 + (col & 3)]);
                    hn[(size_t)(frow * 2) * HH + j0 + col] = l0;
                }
            }
        }

        if (t < TT - 1) { grid_sync(ph * NBLK); ++ph; }
    }
}

/* ------------------------------------------------------------------ */
extern "C" void kernel_launch(void* const* d_in, const int* in_sizes, int n_in,
                              void* d_out, int out_size)
{
    const float* x  = (const float*)d_in[0];
    const float* h0 = (const float*)d_in[1];
    const float* Wi = (const float*)d_in[2];
    const float* bi = (const float*)d_in[3];
    const float* Wh = (const float*)d_in[4];
    const float* bh = (const float*)d_in[5];
    float* out = (float*)d_out;

    dim3 g2(16, 256);
    pre_gemm<<<g2, 256>>>(x, Wi, bi);

    size_t smem = 8192 * sizeof(float4) + (32 * 8 * 65 + 64) * sizeof(float);  /* ~198 KB */
    cudaFuncSetAttribute(rnn_persist, cudaFuncAttributeMaxDynamicSharedMemorySize, (int)smem);
    rnn_persist<<<NBLK, NTH, smem>>>(h0, Wi, bi, Wh, bh, out);
}

// round 9
// speedup vs baseline: 1.2496x; 1.0356x over previous
#include <cuda_runtime.h>
#include <math.h>

#define BB   128
#define TT   256
#define HH   1024
#define KG   256     /* HH/4 feature-groups */
#define NBLK 128
#define NJ   8       /* output cols per CTA */
#define NTH  512
#define K4G  32      /* k4 steps per K-group (8 groups of 64 slots) */

typedef unsigned long long u64;

/* Scratch (static device globals; no runtime allocation). */
__device__ float4 g_pre0[(size_t)TT * KG * BB];   /* [t][j4][b] */
__device__ float4 g_h0buf[2][KG * BB];            /* layer-0 hidden, double buffered, [k4][b] */
__device__ float4 g_h1buf[2][KG * BB];            /* layer-1 hidden */
__device__ unsigned int g_flags[NBLK * 64];       /* per-CTA barrier flags, 256B stride */

/* ---------------- packed fp32x2 helpers (FFMA2 path) ---------------- */
__device__ __forceinline__ u64 fma2(u64 a, u64 b, u64 c) {
    u64 d; asm("fma.rn.f32x2 %0, %1, %2, %3;" : "=l"(d) : "l"(a), "l"(b), "l"(c)); return d;
}
__device__ __forceinline__ u64 pack2(float x, float y) {
    u64 r; asm("mov.b64 %0, {%1, %2};" : "=l"(r) : "f"(x), "f"(y)); return r;
}
__device__ __forceinline__ float2 unpk(u64 v) {
    float2 f; asm("mov.b64 {%0, %1}, %2;" : "=f"(f.x), "=f"(f.y) : "l"(v)); return f;
}
__device__ __forceinline__ void ldcg2(const float4* p, u64& x, u64& y) {
    asm("ld.global.cg.v2.u64 {%0,%1}, [%2];" : "=l"(x), "=l"(y) : "l"(p));
}

/* ------------------------------------------------------------------ */
/* Kernel 1: pre0[t][j][b] = sum_k x[b][t][k]*Wi0[k][j] + bi0[j]       */
/* ------------------------------------------------------------------ */
__global__ __launch_bounds__(256) void pre_gemm(const float* __restrict__ x,
                                                const float* __restrict__ Wi,
                                                const float* __restrict__ bi)
{
    /* Reset barrier flags for this launch (graph replays reuse state). */
    if (blockIdx.x == 0 && blockIdx.y == 0 && threadIdx.x < NBLK)
        g_flags[threadIdx.x * 64] = 0u;

    __shared__ float  sA[32][129];
    __shared__ float4 sB[32 * 16];

    const int t     = blockIdx.y;
    const int jbase = blockIdx.x * 64;
    const int tid   = threadIdx.x;
    const int rid   = tid & 31;
    const int cid   = tid >> 5;

    u64 acc[4][4];
#pragma unroll
    for (int i = 0; i < 4; ++i)
#pragma unroll
        for (int j = 0; j < 4; ++j) acc[i][j] = 0ull;

    const int brow = tid >> 1;
    const int half = tid & 1;

    for (int k0 = 0; k0 < HH; k0 += 32) {
        __syncthreads();
        const float* xs = x + ((size_t)brow * TT + t) * HH + k0 + half * 16;
#pragma unroll
        for (int q = 0; q < 4; ++q) {
            float4 v = *(const float4*)(xs + 4 * q);
            int kk = half * 16 + 4 * q;
            sA[kk + 0][brow] = v.x; sA[kk + 1][brow] = v.y;
            sA[kk + 2][brow] = v.z; sA[kk + 3][brow] = v.w;
        }
#pragma unroll
        for (int q = 0; q < 2; ++q) {
            int idx = tid + 256 * q;
            int kk = idx >> 4, jf = idx & 15;
            sB[idx] = *(const float4*)(Wi + (size_t)(k0 + kk) * HH + jbase + 4 * jf);
        }
        __syncthreads();

#pragma unroll
        for (int kk = 0; kk < 32; ++kk) {
            float a0 = sA[kk][rid], a1 = sA[kk][rid + 32];
            float a2 = sA[kk][rid + 64], a3 = sA[kk][rid + 96];
            const ulonglong2* bp = (const ulonglong2*)&sB[kk * 16 + cid * 2];
            ulonglong2 bb0 = bp[0];
            ulonglong2 bb1 = bp[1];
            u64 ad0 = pack2(a0, a0), ad1 = pack2(a1, a1);
            u64 ad2 = pack2(a2, a2), ad3 = pack2(a3, a3);
            acc[0][0] = fma2(ad0, bb0.x, acc[0][0]); acc[0][1] = fma2(ad0, bb0.y, acc[0][1]);
            acc[0][2] = fma2(ad0, bb1.x, acc[0][2]); acc[0][3] = fma2(ad0, bb1.y, acc[0][3]);
            acc[1][0] = fma2(ad1, bb0.x, acc[1][0]); acc[1][1] = fma2(ad1, bb0.y, acc[1][1]);
            acc[1][2] = fma2(ad1, bb1.x, acc[1][2]); acc[1][3] = fma2(ad1, bb1.y, acc[1][3]);
            acc[2][0] = fma2(ad2, bb0.x, acc[2][0]); acc[2][1] = fma2(ad2, bb0.y, acc[2][1]);
            acc[2][2] = fma2(ad2, bb1.x, acc[2][2]); acc[2][3] = fma2(ad2, bb1.y, acc[2][3]);
            acc[3][0] = fma2(ad3, bb0.x, acc[3][0]); acc[3][1] = fma2(ad3, bb0.y, acc[3][1]);
            acc[3][2] = fma2(ad3, bb1.x, acc[3][2]); acc[3][3] = fma2(ad3, bb1.y, acc[3][3]);
        }
    }

    float biv[8];
#pragma unroll
    for (int j = 0; j < 8; ++j) biv[j] = __ldg(&bi[jbase + cid * 8 + j]);

    const int jg = (jbase + cid * 8) >> 2;
#pragma unroll
    for (int i = 0; i < 4; ++i) {
        int row = rid + 32 * i;
#pragma unroll
        for (int gq = 0; gq < 2; ++gq) {
            float2 u0 = unpk(acc[i][2 * gq]);
            float2 u1 = unpk(acc[i][2 * gq + 1]);
            float4 v;
            v.x = u0.x + biv[4 * gq + 0];
            v.y = u0.y + biv[4 * gq + 1];
            v.z = u1.x + biv[4 * gq + 2];
            v.w = u1.y + biv[4 * gq + 3];
            g_pre0[((size_t)t * KG + jg + gq) * BB + row] = v;
        }
    }
}

/* ------------------------------------------------------------------ */
/* Distributed grid barrier: per-CTA flag (256B stride, no atomics).   */
/* Arrive: thread0 release-stores ph to own flag. Wait: threads 0..127 */
/* each acquire-poll one flag. Monotonic ph; flags reset by pre_gemm.  */
/* ------------------------------------------------------------------ */
__device__ __forceinline__ void grid_arrive(int cta, int th, unsigned int ph)
{
    __syncthreads();   /* all CTA writes (h0buf/h1buf) done */
    if (th == 0) {
        asm volatile("st.release.gpu.global.u32 [%0], %1;"
                     :: "l"(&g_flags[cta * 64]), "r"(ph) : "memory");
    }
}
__device__ __forceinline__ void grid_wait(int th, unsigned int ph)
{
    if (th < NBLK) {
        unsigned int v;
        do {
            asm volatile("ld.acquire.gpu.global.u32 %0, [%1];"
                         : "=r"(v) : "l"(&g_flags[th * 64]) : "memory");
        } while (v < ph);
    }
    __syncthreads();
}

#define RIDX(i, g, s) ((((i) * 8 + (g)) * 65) + (s))

/* jj-body macros (loop1 feeds acc1 via Wi1 + acc0 via Wh0; loop2 feeds acc1 via Wh1) */
#define JJ1(cax, cay, cbx, cby, OFF)                                              \
    {                                                                             \
        int off_ = (OFF);                                                         \
        _Pragma("unroll")                                                         \
        for (int jj = 0; jj < NJ; ++jj) {                                         \
            ulonglong2 w1 = *(const ulonglong2*)&sWi1[jj * 256 + off_];           \
            acc1r0[jj] = fma2(cax, w1.x, fma2(cay, w1.y, acc1r0[jj]));            \
            acc1r1[jj] = fma2(cbx, w1.x, fma2(cby, w1.y, acc1r1[jj]));            \
            ulonglong2 w0 = *(const ulonglong2*)&sWh0[jj * 256 + off_];           \
            acc0r0[jj] = fma2(cax, w0.x, fma2(cay, w0.y, acc0r0[jj]));            \
            acc0r1[jj] = fma2(cbx, w0.x, fma2(cby, w0.y, acc0r1[jj]));            \
        }                                                                         \
    }

#define JJ2(cax, cay, cbx, cby, OFF)                                              \
    {                                                                             \
        int off_ = (OFF);                                                         \
        _Pragma("unroll")                                                         \
        for (int jj = 0; jj < NJ; ++jj) {                                         \
            ulonglong2 w = *(const ulonglong2*)&sWh1[jj * 256 + off_];            \
            acc1r0[jj] = fma2(cax, w.x, fma2(cay, w.y, acc1r0[jj]));              \
            acc1r1[jj] = fma2(cbx, w.x, fma2(cby, w.y, acc1r1[jj]));              \
        }                                                                         \
    }

/* ------------------------------------------------------------------ */
/* Kernel 2: persistent weight-stationary RNN, FFMA2, 512 threads.     */
/* thread = (K-group g of 8, row-slot of 64); rows slot and slot+64.   */
/* Depth-2 prefetch on A-loads; pre0[t+1] hoisted; distributed barrier.*/
/* ------------------------------------------------------------------ */
__global__ __launch_bounds__(NTH, 1) void rnn_persist(const float* __restrict__ h0,
                                                      const float* __restrict__ Wi,
                                                      const float* __restrict__ bi,
                                                      const float* __restrict__ Wh,
                                                      const float* __restrict__ bh,
                                                      float* __restrict__ out)
{
    extern __shared__ float4 smem4[];
    float4* sWh0 = smem4;              /* [8][256] col-slices */
    float4* sWi1 = smem4 + 2048;
    float4* sWh1 = smem4 + 4096;
    float*  sred = (float*)(smem4 + 6144);          /* [32][8][65] partials */
    float*  sdot = sred + 32 * 8 * 65;              /* [8][8] init dot */

    const int cta  = blockIdx.x;
    const int th   = threadIdx.x;
    const int g    = th >> 6;          /* K group 0..7 */
    const int slot = th & 63;          /* row slot: rows slot, slot+64 */
    const int j0   = cta * NJ;

    /* final-pass mapping (all 512 threads): */
    const int frow = th >> 2;          /* 0..127 */
    const int c0   = (th & 3) * 2;     /* cols c0, c0+1 of this CTA's 8 */
    const int fslot = frow & 63;
    const int frh   = frow >> 6;
    const int fjg4  = (j0 + c0) >> 2;
    const int fcl   = c0 & 3;

    const float* Wi1g = Wi + (size_t)HH * HH;
    const float* Wh1g = Wh + (size_t)HH * HH;

    /* One-time: gather weight column slices into SMEM (float4 over k). */
    for (int idx = th; idx < 2048; idx += NTH) {
        int jl = idx >> 8, k4 = idx & 255;
        int j = j0 + jl;
        int kb = k4 * 4;
        sWh0[idx] = make_float4(Wh[(size_t)(kb + 0) * HH + j], Wh[(size_t)(kb + 1) * HH + j],
                                Wh[(size_t)(kb + 2) * HH + j], Wh[(size_t)(kb + 3) * HH + j]);
        sWi1[idx] = make_float4(Wi1g[(size_t)(kb + 0) * HH + j], Wi1g[(size_t)(kb + 1) * HH + j],
                                Wi1g[(size_t)(kb + 2) * HH + j], Wi1g[(size_t)(kb + 3) * HH + j]);
        sWh1[idx] = make_float4(Wh1g[(size_t)(kb + 0) * HH + j], Wh1g[(size_t)(kb + 1) * HH + j],
                                Wh1g[(size_t)(kb + 2) * HH + j], Wh1g[(size_t)(kb + 3) * HH + j]);
    }

    float bs1[2], b0r[2];
#pragma unroll
    for (int e = 0; e < 2; ++e) {
        bs1[e] = __ldg(&bi[HH + j0 + c0 + e]) + __ldg(&bh[HH + j0 + c0 + e]);
        b0r[e] = __ldg(&bh[j0 + c0 + e]);
    }

    /* h1 init: CTA covers k4 in [2*cta, 2*cta+2), broadcast h0 layer 1. */
    for (int idx = th; idx < 2 * BB; idx += NTH) {
        int k4l = idx >> 7, b = idx & 127;
        g_h1buf[1][(2 * cta + k4l) * BB + b] = *(const float4*)(h0 + HH + 4 * (2 * cta + k4l));
    }
    __syncthreads();

    /* hn0[0] init: dot0[col] = h0_l0 @ Wh0 (shared over batch rows). */
    {
        u64 d[NJ];
#pragma unroll
        for (int jj = 0; jj < NJ; ++jj) d[jj] = 0ull;
        for (int kk = 0; kk < K4G; ++kk) {
            int off = g * K4G + kk;
            ulonglong2 a = *(const ulonglong2*)(h0 + 4 * off);
#pragma unroll
            for (int jj = 0; jj < NJ; ++jj) {
                ulonglong2 w = *(const ulonglong2*)&sWh0[jj * 256 + off];
                d[jj] = fma2(a.x, w.x, fma2(a.y, w.y, d[jj]));
            }
        }
        if (slot == 0) {
#pragma unroll
            for (int jj = 0; jj < NJ; ++jj) {
                float2 f = unpk(d[jj]);
                sdot[g * 8 + jj] = f.x + f.y;
            }
        }
        __syncthreads();
        const float* preF = (const float*)g_pre0;
#pragma unroll
        for (int e = 0; e < 2; ++e) {
            int col = c0 + e;
            float dv = 0.0f;
#pragma unroll
            for (int g2 = 0; g2 < 8; ++g2) dv += sdot[g2 * 8 + col];
            int jg4 = (j0 + col) >> 2;
            float pre = preF[((size_t)jg4 * BB + frow) * 4 + (col & 3)];
            ((float*)g_h0buf[0])[((size_t)jg4 * BB + frow) * 4 + (col & 3)] = tanhf(pre + dv + b0r[e]);
        }
    }

    unsigned int ph = 1;
    grid_arrive(cta, th, ph);
    grid_wait(th, ph);
    ++ph;

    for (int t = 0; t < TT; ++t) {
        const float4* A0 = g_h0buf[t & 1];
        const float4* A1 = g_h1buf[(t + 1) & 1];
        const float4* p0 = A0 + (size_t)g * K4G * BB + slot;
        const float4* p1 = A1 + (size_t)g * K4G * BB + slot;

        /* Hoisted prefetch: next-step pre0 (cols c0, c0+1 are adjacent). */
        float2 pn = make_float2(0.0f, 0.0f);
        if (t < TT - 1) {
            const float* pp = (const float*)g_pre0 +
                ((size_t)((size_t)(t + 1) * KG + fjg4) * BB + frow) * 4 + fcl;
            asm("ld.global.cg.v2.f32 {%0,%1}, [%2];" : "=f"(pn.x), "=f"(pn.y) : "l"(pp));
        }

        u64 acc1r0[NJ], acc1r1[NJ], acc0r0[NJ], acc0r1[NJ];
#pragma unroll
        for (int jj = 0; jj < NJ; ++jj) {
            acc1r0[jj] = 0ull; acc1r1[jj] = 0ull;
            acc0r0[jj] = 0ull; acc0r1[jj] = 0ull;
        }

        /* Loop 1: A0 feeds Wi1 (acc1) and Wh0 (acc0). Depth-2 prefetch. */
        {
            u64 A0x, A0y, B0x, B0y, A1x, A1y, B1x, B1y;
            ldcg2(p0,          A0x, A0y); ldcg2(p0 + 64,      B0x, B0y);
            ldcg2(p0 + BB,     A1x, A1y); ldcg2(p0 + BB + 64, B1x, B1y);
#pragma unroll 1
            for (int kk = 0; kk < K4G; kk += 2) {
                int off = g * K4G + kk;
                JJ1(A0x, A0y, B0x, B0y, off);
                if (kk + 2 < K4G) {
                    ldcg2(p0 + (kk + 2) * BB,      A0x, A0y);
                    ldcg2(p0 + (kk + 2) * BB + 64, B0x, B0y);
                }
                JJ1(A1x, A1y, B1x, B1y, off + 1);
                if (kk + 3 < K4G) {
                    ldcg2(p0 + (kk + 3) * BB,      A1x, A1y);
                    ldcg2(p0 + (kk + 3) * BB + 64, B1x, B1y);
                }
            }
        }
        /* Loop 2: A1 feeds Wh1 (acc1). Depth-2 prefetch. */
        {
            u64 A0x, A0y, B0x, B0y, A1x, A1y, B1x, B1y;
            ldcg2(p1,          A0x, A0y); ldcg2(p1 + 64,      B0x, B0y);
            ldcg2(p1 + BB,     A1x, A1y); ldcg2(p1 + BB + 64, B1x, B1y);
#pragma unroll 1
            for (int kk = 0; kk < K4G; kk += 2) {
                int off = g * K4G + kk;
                JJ2(A0x, A0y, B0x, B0y, off);
                if (kk + 2 < K4G) {
                    ldcg2(p1 + (kk + 2) * BB,      A0x, A0y);
                    ldcg2(p1 + (kk + 2) * BB + 64, B0x, B0y);
                }
                JJ2(A1x, A1y, B1x, B1y, off + 1);
                if (kk + 3 < K4G) {
                    ldcg2(p1 + (kk + 3) * BB,      A1x, A1y);
                    ldcg2(p1 + (kk + 3) * BB + 64, B1x, B1y);
                }
            }
        }

        /* Collapse (lo+hi) and write partials for 8-way K reduction. */
#pragma unroll
        for (int jj = 0; jj < NJ; ++jj) {
            float2 v;
            v = unpk(acc1r0[jj]); sred[RIDX(jj,      g, slot)] = v.x + v.y;
            v = unpk(acc1r1[jj]); sred[RIDX(jj + 8,  g, slot)] = v.x + v.y;
            v = unpk(acc0r0[jj]); sred[RIDX(jj + 16, g, slot)] = v.x + v.y;
            v = unpk(acc0r1[jj]); sred[RIDX(jj + 24, g, slot)] = v.x + v.y;
        }
        __syncthreads();

        /* Final pass: compute outputs, publish recurrent state FIRST,    */
        /* arrive, then overlap the out[] store with the barrier wait.    */
        {
            float* h1w = (float*)g_h1buf[t & 1];
            float y[2];
#pragma unroll
            for (int e = 0; e < 2; ++e) {
                int col = c0 + e;
                float s1 = 0.0f;
#pragma unroll
                for (int g2 = 0; g2 < 8; ++g2) s1 += sred[RIDX(col + 8 * frh, g2, fslot)];
                y[e] = tanhf(s1 + bs1[e]);
                int jg4 = (j0 + col) >> 2;
                h1w[((size_t)jg4 * BB + frow) * 4 + (col & 3)] = y[e];

                if (t < TT - 1) {
                    float s0 = 0.0f;
#pragma unroll
                    for (int g2 = 0; g2 < 8; ++g2) s0 += sred[RIDX(col + 8 * (2 + frh), g2, fslot)];
                    float pre = (e == 0) ? pn.x : pn.y;
                    ((float*)g_h0buf[(t + 1) & 1])[((size_t)jg4 * BB + frow) * 4 + (col & 3)] =
                        tanhf(s0 + pre + b0r[e]);
                }
            }

            if (t < TT - 1) {
                grid_arrive(cta, th, ph);
                /* overlapped with barrier wait: */
                out[((size_t)frow * TT + t) * HH + j0 + c0]     = y[0];
                out[((size_t)frow * TT + t) * HH + j0 + c0 + 1] = y[1];
                grid_wait(th, ph);
                ++ph;
            } else {
                out[((size_t)frow * TT + t) * HH + j0 + c0]     = y[0];
                out[((size_t)frow * TT + t) * HH + j0 + c0 + 1] = y[1];
                float* hn = out + (size_t)BB * TT * HH;
                hn[(size_t)(frow * 2 + 1) * HH + j0 + c0]     = y[0];
                hn[(size_t)(frow * 2 + 1) * HH + j0 + c0 + 1] = y[1];
#pragma unroll
                for (int e = 0; e < 2; ++e) {
                    int col = c0 + e;
                    int jg4 = (j0 + col) >> 2;
                    float l0 = ((const float*)g_h0buf[t & 1])[((size_t)jg4 * BB + frow) * 4 + (col & 3)];
                    hn[(size_t)(frow * 2) * HH + j0 + col] = l0;
                }
            }
        }
    }
}

/* ------------------------------------------------------------------ */
extern "C" void kernel_launch(void* const* d_in, const int* in_sizes, int n_in,
                              void* d_out, int out_size)
{
    const float* x  = (const float*)d_in[0];
    const float* h0 = (const float*)d_in[1];
    const float* Wi = (const float*)d_in[2];
    const float* bi = (const float*)d_in[3];
    const float* Wh = (const float*)d_in[4];
    const float* bh = (const float*)d_in[5];
    float* out = (float*)d_out;

    dim3 g2(16, 256);
    pre_gemm<<<g2, 256>>>(x, Wi, bi);

    size_t smem = 6144 * sizeof(float4) + (32 * 8 * 65 + 64) * sizeof(float);  /* ~161.5 KB */
    cudaFuncSetAttribute(rnn_persist, cudaFuncAttributeMaxDynamicSharedMemorySize, (int)smem);
    rnn_persist<<<NBLK, NTH, smem>>>(h0, Wi, bi, Wh, bh, out);
}

// round 10
// speedup vs baseline: 1.2596x; 1.0080x over previous
#include <cuda_runtime.h>
#include <math.h>

#define BB   128
#define TT   256
#define HH   1024
#define KG   256     /* HH/4 feature-groups */
#define NBLK 128
#define NJ   8       /* output cols per CTA */
#define NTH  512
#define K4G  32      /* k4 steps per K-group (8 groups of 64 slots) */

typedef unsigned long long u64;

/* Scratch (static device globals; no runtime allocation). */
__device__ float4 g_pre0[(size_t)TT * KG * BB];   /* [t][j4][b] */
__device__ float4 g_h0buf[2][KG * BB];            /* layer-0 hidden, double buffered, [k4][b] */
__device__ float4 g_h1buf[2][KG * BB];            /* layer-1 hidden */
__device__ unsigned int g_flags[NBLK * 64];       /* per-CTA barrier flags, 256B stride */

/* ---------------- packed fp32x2 helpers (FFMA2 path) ---------------- */
__device__ __forceinline__ u64 fma2(u64 a, u64 b, u64 c) {
    u64 d; asm("fma.rn.f32x2 %0, %1, %2, %3;" : "=l"(d) : "l"(a), "l"(b), "l"(c)); return d;
}
__device__ __forceinline__ u64 pack2(float x, float y) {
    u64 r; asm("mov.b64 %0, {%1, %2};" : "=l"(r) : "f"(x), "f"(y)); return r;
}
__device__ __forceinline__ float2 unpk(u64 v) {
    float2 f; asm("mov.b64 {%0, %1}, %2;" : "=f"(f.x), "=f"(f.y) : "l"(v)); return f;
}
__device__ __forceinline__ void ldcg2(const float4* p, u64& x, u64& y) {
    asm("ld.global.cg.v2.u64 {%0,%1}, [%2];" : "=l"(x), "=l"(y) : "l"(p));
}

/* ------------------------------------------------------------------ */
/* Kernel 1: pre0[t][j][b] = sum_k x[b][t][k]*Wi0[k][j] + bi0[j]       */
/* ------------------------------------------------------------------ */
__global__ __launch_bounds__(256) void pre_gemm(const float* __restrict__ x,
                                                const float* __restrict__ Wi,
                                                const float* __restrict__ bi)
{
    /* Reset barrier flags for this launch (graph replays reuse state). */
    if (blockIdx.x == 0 && blockIdx.y == 0 && threadIdx.x < NBLK)
        g_flags[threadIdx.x * 64] = 0u;

    __shared__ float  sA[32][129];
    __shared__ float4 sB[32 * 16];

    const int t     = blockIdx.y;
    const int jbase = blockIdx.x * 64;
    const int tid   = threadIdx.x;
    const int rid   = tid & 31;
    const int cid   = tid >> 5;

    u64 acc[4][4];
#pragma unroll
    for (int i = 0; i < 4; ++i)
#pragma unroll
        for (int j = 0; j < 4; ++j) acc[i][j] = 0ull;

    const int brow = tid >> 1;
    const int half = tid & 1;

    for (int k0 = 0; k0 < HH; k0 += 32) {
        __syncthreads();
        const float* xs = x + ((size_t)brow * TT + t) * HH + k0 + half * 16;
#pragma unroll
        for (int q = 0; q < 4; ++q) {
            float4 v = *(const float4*)(xs + 4 * q);
            int kk = half * 16 + 4 * q;
            sA[kk + 0][brow] = v.x; sA[kk + 1][brow] = v.y;
            sA[kk + 2][brow] = v.z; sA[kk + 3][brow] = v.w;
        }
#pragma unroll
        for (int q = 0; q < 2; ++q) {
            int idx = tid + 256 * q;
            int kk = idx >> 4, jf = idx & 15;
            sB[idx] = *(const float4*)(Wi + (size_t)(k0 + kk) * HH + jbase + 4 * jf);
        }
        __syncthreads();

#pragma unroll
        for (int kk = 0; kk < 32; ++kk) {
            float a0 = sA[kk][rid], a1 = sA[kk][rid + 32];
            float a2 = sA[kk][rid + 64], a3 = sA[kk][rid + 96];
            const ulonglong2* bp = (const ulonglong2*)&sB[kk * 16 + cid * 2];
            ulonglong2 bb0 = bp[0];
            ulonglong2 bb1 = bp[1];
            u64 ad0 = pack2(a0, a0), ad1 = pack2(a1, a1);
            u64 ad2 = pack2(a2, a2), ad3 = pack2(a3, a3);
            acc[0][0] = fma2(ad0, bb0.x, acc[0][0]); acc[0][1] = fma2(ad0, bb0.y, acc[0][1]);
            acc[0][2] = fma2(ad0, bb1.x, acc[0][2]); acc[0][3] = fma2(ad0, bb1.y, acc[0][3]);
            acc[1][0] = fma2(ad1, bb0.x, acc[1][0]); acc[1][1] = fma2(ad1, bb0.y, acc[1][1]);
            acc[1][2] = fma2(ad1, bb1.x, acc[1][2]); acc[1][3] = fma2(ad1, bb1.y, acc[1][3]);
            acc[2][0] = fma2(ad2, bb0.x, acc[2][0]); acc[2][1] = fma2(ad2, bb0.y, acc[2][1]);
            acc[2][2] = fma2(ad2, bb1.x, acc[2][2]); acc[2][3] = fma2(ad2, bb1.y, acc[2][3]);
            acc[3][0] = fma2(ad3, bb0.x, acc[3][0]); acc[3][1] = fma2(ad3, bb0.y, acc[3][1]);
            acc[3][2] = fma2(ad3, bb1.x, acc[3][2]); acc[3][3] = fma2(ad3, bb1.y, acc[3][3]);
        }
    }

    float biv[8];
#pragma unroll
    for (int j = 0; j < 8; ++j) biv[j] = __ldg(&bi[jbase + cid * 8 + j]);

    const int jg = (jbase + cid * 8) >> 2;
#pragma unroll
    for (int i = 0; i < 4; ++i) {
        int row = rid + 32 * i;
#pragma unroll
        for (int gq = 0; gq < 2; ++gq) {
            float2 u0 = unpk(acc[i][2 * gq]);
            float2 u1 = unpk(acc[i][2 * gq + 1]);
            float4 v;
            v.x = u0.x + biv[4 * gq + 0];
            v.y = u0.y + biv[4 * gq + 1];
            v.z = u1.x + biv[4 * gq + 2];
            v.w = u1.y + biv[4 * gq + 3];
            g_pre0[((size_t)t * KG + jg + gq) * BB + row] = v;
        }
    }
}

/* ------------------------------------------------------------------ */
/* Distributed grid barrier: per-CTA flag (256B stride, no atomics).   */
/* ------------------------------------------------------------------ */
__device__ __forceinline__ void grid_arrive(int cta, int th, unsigned int ph)
{
    __syncthreads();   /* all CTA writes (h0buf/h1buf) done */
    if (th == 0) {
        asm volatile("st.release.gpu.global.u32 [%0], %1;"
                     :: "l"(&g_flags[cta * 64]), "r"(ph) : "memory");
    }
}
__device__ __forceinline__ void grid_wait(int th, unsigned int ph)
{
    if (th < NBLK) {
        unsigned int v;
        do {
            asm volatile("ld.acquire.gpu.global.u32 %0, [%1];"
                         : "=r"(v) : "l"(&g_flags[th * 64]) : "memory");
        } while (v < ph);
    }
    __syncthreads();
}

#define RIDX(i, g, s) ((((i) * 8 + (g)) * 65) + (s))

/* Weights interleaved, power-of-2 stride: sWall[k4*32 + m],
   m = 0..7 Wi1 col, 8..15 Wh1 col, 16..23 Wh0 col, 24..31 pad.
   Per kk: one pointer (kk<<5), all 24 LDS at immediate offsets.       */

/* Load fused A regs (A0 rows slot/slot+64, A1 rows slot/slot+64). */
#define LOADF(R, KK)                                          \
    ldcg2(p0 + (KK) * BB,      R##0x, R##0y);                 \
    ldcg2(p0 + (KK) * BB + 64, R##1x, R##1y);                 \
    ldcg2(p1 + (KK) * BB,      R##2x, R##2y);                 \
    ldcg2(p1 + (KK) * BB + 64, R##3x, R##3y);

/* Fused body: 8 jj x {Wi1@A0 -> acc1, Wh1@A1 -> acc1, Wh0@A0 -> acc0}. */
#define BODYF(R, KK)                                                              \
    {                                                                             \
        const ulonglong2* wk_ = (const ulonglong2*)(wbase + ((KK) << 5));         \
        _Pragma("unroll")                                                         \
        for (int jj = 0; jj < NJ; ++jj) {                                         \
            ulonglong2 w1 = wk_[jj];                                              \
            acc1r0[jj] = fma2(R##0x, w1.x, fma2(R##0y, w1.y, acc1r0[jj]));        \
            acc1r1[jj] = fma2(R##1x, w1.x, fma2(R##1y, w1.y, acc1r1[jj]));        \
            ulonglong2 wh1 = wk_[8 + jj];                                         \
            acc1r0[jj] = fma2(R##2x, wh1.x, fma2(R##2y, wh1.y, acc1r0[jj]));      \
            acc1r1[jj] = fma2(R##3x, wh1.x, fma2(R##3y, wh1.y, acc1r1[jj]));      \
            ulonglong2 wh0 = wk_[16 + jj];                                        \
            acc0r0[jj] = fma2(R##0x, wh0.x, fma2(R##0y, wh0.y, acc0r0[jj]));      \
            acc0r1[jj] = fma2(R##1x, wh0.x, fma2(R##1y, wh0.y, acc0r1[jj]));      \
        }                                                                         \
    }

/* ------------------------------------------------------------------ */
/* Kernel 2: persistent weight-stationary RNN, FFMA2, 512 threads.     */
/* thread = (K-group g of 8, row-slot of 64); rows slot and slot+64.   */
/* Fused K-loop (8 LDG in flight), pow2-interleaved weights,           */
/* distributed barrier, hoisted pre0 prefetch.                         */
/* ------------------------------------------------------------------ */
__global__ __launch_bounds__(NTH, 1) void rnn_persist(const float* __restrict__ h0,
                                                      const float* __restrict__ Wi,
                                                      const float* __restrict__ bi,
                                                      const float* __restrict__ Wh,
                                                      const float* __restrict__ bh,
                                                      float* __restrict__ out)
{
    extern __shared__ float4 smem4[];
    float4* sWall = smem4;                          /* [256 k4][32] interleaved */
    float*  sred = (float*)(smem4 + 8192);          /* [32][8][65] partials */
    float*  sdot = sred + 32 * 8 * 65;              /* [8][8] init dot */

    const int cta  = blockIdx.x;
    const int th   = threadIdx.x;
    const int g    = th >> 6;          /* K group 0..7 */
    const int slot = th & 63;          /* row slot: rows slot, slot+64 */
    const int j0   = cta * NJ;

    /* final-pass mapping (all 512 threads): */
    const int frow = th >> 2;          /* 0..127 */
    const int c0   = (th & 3) * 2;     /* cols c0, c0+1 of this CTA's 8 */
    const int fslot = frow & 63;
    const int frh   = frow >> 6;
    const int fjg4  = (j0 + c0) >> 2;
    const int fcl   = c0 & 3;

    const float* Wi1g = Wi + (size_t)HH * HH;
    const float* Wh1g = Wh + (size_t)HH * HH;

    /* One-time: interleaved weight gather. m: 0-7 Wi1, 8-15 Wh1, 16-23 Wh0. */
    for (int idx = th; idx < 8192; idx += NTH) {
        int k4 = idx >> 5, m = idx & 31;
        if (m >= 24) continue;
        int j  = j0 + (m & 7);
        int kb = k4 * 4;
        const float* M = (m < 8) ? Wi1g : (m < 16) ? Wh1g : Wh;
        sWall[idx] = make_float4(M[(size_t)(kb + 0) * HH + j], M[(size_t)(kb + 1) * HH + j],
                                 M[(size_t)(kb + 2) * HH + j], M[(size_t)(kb + 3) * HH + j]);
    }

    float bs1[2], b0r[2];
#pragma unroll
    for (int e = 0; e < 2; ++e) {
        bs1[e] = __ldg(&bi[HH + j0 + c0 + e]) + __ldg(&bh[HH + j0 + c0 + e]);
        b0r[e] = __ldg(&bh[j0 + c0 + e]);
    }

    /* h1 init: CTA covers k4 in [2*cta, 2*cta+2), broadcast h0 layer 1. */
    for (int idx = th; idx < 2 * BB; idx += NTH) {
        int k4l = idx >> 7, b = idx & 127;
        g_h1buf[1][(2 * cta + k4l) * BB + b] = *(const float4*)(h0 + HH + 4 * (2 * cta + k4l));
    }
    __syncthreads();

    /* hn0[0] init: dot0[col] = h0_l0 @ Wh0 (shared over batch rows). */
    {
        u64 d[NJ];
#pragma unroll
        for (int jj = 0; jj < NJ; ++jj) d[jj] = 0ull;
        for (int kk = 0; kk < K4G; ++kk) {
            int off = g * K4G + kk;
            ulonglong2 a = *(const ulonglong2*)(h0 + 4 * off);
#pragma unroll
            for (int jj = 0; jj < NJ; ++jj) {
                ulonglong2 w = *(const ulonglong2*)&sWall[(off << 5) + 16 + jj];
                d[jj] = fma2(a.x, w.x, fma2(a.y, w.y, d[jj]));
            }
        }
        if (slot == 0) {
#pragma unroll
            for (int jj = 0; jj < NJ; ++jj) {
                float2 f = unpk(d[jj]);
                sdot[g * 8 + jj] = f.x + f.y;
            }
        }
        __syncthreads();
        const float* preF = (const float*)g_pre0;
#pragma unroll
        for (int e = 0; e < 2; ++e) {
            int col = c0 + e;
            float dv = 0.0f;
#pragma unroll
            for (int g2 = 0; g2 < 8; ++g2) dv += sdot[g2 * 8 + col];
            int jg4 = (j0 + col) >> 2;
            float pre = preF[((size_t)jg4 * BB + frow) * 4 + (col & 3)];
            ((float*)g_h0buf[0])[((size_t)jg4 * BB + frow) * 4 + (col & 3)] = tanhf(pre + dv + b0r[e]);
        }
    }

    unsigned int ph = 1;
    grid_arrive(cta, th, ph);
    grid_wait(th, ph);
    ++ph;

    const float4* wbase = sWall + ((size_t)g * K4G << 5);

    for (int t = 0; t < TT; ++t) {
        const float4* p0 = g_h0buf[t & 1]       + (size_t)g * K4G * BB + slot;
        const float4* p1 = g_h1buf[(t + 1) & 1] + (size_t)g * K4G * BB + slot;

        /* Hoisted prefetch: next-step pre0 (cols c0, c0+1 are adjacent). */
        float2 pn = make_float2(0.0f, 0.0f);
        if (t < TT - 1) {
            const float* pp = (const float*)g_pre0 +
                ((size_t)((size_t)(t + 1) * KG + fjg4) * BB + frow) * 4 + fcl;
            asm("ld.global.cg.v2.f32 {%0,%1}, [%2];" : "=f"(pn.x), "=f"(pn.y) : "l"(pp));
        }

        u64 acc1r0[NJ], acc1r1[NJ], acc0r0[NJ], acc0r1[NJ];
#pragma unroll
        for (int jj = 0; jj < NJ; ++jj) {
            acc1r0[jj] = 0ull; acc1r1[jj] = 0ull;
            acc0r0[jj] = 0ull; acc0r1[jj] = 0ull;
        }

        /* Fused K loop: depth-2 pipeline, 8 LDG.128 in flight. */
        {
            u64 Pa0x, Pa0y, Pa1x, Pa1y, Pa2x, Pa2y, Pa3x, Pa3y;
            u64 Pb0x, Pb0y, Pb1x, Pb1y, Pb2x, Pb2y, Pb3x, Pb3y;
            LOADF(Pa, 0);
#pragma unroll 1
            for (int kk = 0; kk < K4G; kk += 2) {
                LOADF(Pb, kk + 1);
                BODYF(Pa, kk);
                if (kk + 2 < K4G) { LOADF(Pa, kk + 2); }
                BODYF(Pb, kk + 1);
            }
        }

        /* Collapse (lo+hi) and write partials for 8-way K reduction. */
#pragma unroll
        for (int jj = 0; jj < NJ; ++jj) {
            float2 v;
            v = unpk(acc1r0[jj]); sred[RIDX(jj,      g, slot)] = v.x + v.y;
            v = unpk(acc1r1[jj]); sred[RIDX(jj + 8,  g, slot)] = v.x + v.y;
            v = unpk(acc0r0[jj]); sred[RIDX(jj + 16, g, slot)] = v.x + v.y;
            v = unpk(acc0r1[jj]); sred[RIDX(jj + 24, g, slot)] = v.x + v.y;
        }
        __syncthreads();

        /* Final pass: compute outputs, publish recurrent state FIRST,    */
        /* arrive, then overlap the out[] store with the barrier wait.    */
        {
            float* h1w = (float*)g_h1buf[t & 1];
            float y[2];
#pragma unroll
            for (int e = 0; e < 2; ++e) {
                int col = c0 + e;
                float s1 = 0.0f;
#pragma unroll
                for (int g2 = 0; g2 < 8; ++g2) s1 += sred[RIDX(col + 8 * frh, g2, fslot)];
                y[e] = tanhf(s1 + bs1[e]);
                int jg4 = (j0 + col) >> 2;
                h1w[((size_t)jg4 * BB + frow) * 4 + (col & 3)] = y[e];

                if (t < TT - 1) {
                    float s0 = 0.0f;
#pragma unroll
                    for (int g2 = 0; g2 < 8; ++g2) s0 += sred[RIDX(col + 8 * (2 + frh), g2, fslot)];
                    float pre = (e == 0) ? pn.x : pn.y;
                    ((float*)g_h0buf[(t + 1) & 1])[((size_t)jg4 * BB + frow) * 4 + (col & 3)] =
                        tanhf(s0 + pre + b0r[e]);
                }
            }

            if (t < TT - 1) {
                grid_arrive(cta, th, ph);
                /* overlapped with barrier wait: */
                out[((size_t)frow * TT + t) * HH + j0 + c0]     = y[0];
                out[((size_t)frow * TT + t) * HH + j0 + c0 + 1] = y[1];
                grid_wait(th, ph);
                ++ph;
            } else {
                out[((size_t)frow * TT + t) * HH + j0 + c0]     = y[0];
                out[((size_t)frow * TT + t) * HH + j0 + c0 + 1] = y[1];
                float* hn = out + (size_t)BB * TT * HH;
                hn[(size_t)(frow * 2 + 1) * HH + j0 + c0]     = y[0];
                hn[(size_t)(frow * 2 + 1) * HH + j0 + c0 + 1] = y[1];
#pragma unroll
                for (int e = 0; e < 2; ++e) {
                    int col = c0 + e;
                    int jg4 = (j0 + col) >> 2;
                    float l0 = ((const float*)g_h0buf[t & 1])[((size_t)jg4 * BB + frow) * 4 + (col & 3)];
                    hn[(size_t)(frow * 2) * HH + j0 + col] = l0;
                }
            }
        }
    }
}

/* ------------------------------------------------------------------ */
extern "C" void kernel_launch(void* const* d_in, const int* in_sizes, int n_in,
                              void* d_out, int out_size)
{
    const float* x  = (const float*)d_in[0];
    const float* h0 = (const float*)d_in[1];
    const float* Wi = (const float*)d_in[2];
    const float* bi = (const float*)d_in[3];
    const float* Wh = (const float*)d_in[4];
    const float* bh = (const float*)d_in[5];
    float* out = (float*)d_out;

    dim3 g2(16, 256);
    pre_gemm<<<g2, 256>>>(x, Wi, bi);

    size_t smem = 8192 * sizeof(float4) + (32 * 8 * 65 + 64) * sizeof(float);  /* ~193 KB */
    cudaFuncSetAttribute(rnn_persist, cudaFuncAttributeMaxDynamicSharedMemorySize, (int)smem);
    rnn_persist<<<NBLK, NTH, smem>>>(h0, Wi, bi, Wh, bh, out);
}

// round 11
// speedup vs baseline: 2.3148x; 1.8377x over previous
#include <cuda_runtime.h>
#include <cuda_bf16.h>
#include <math.h>

#define BB   128
#define TT   256
#define HH   1024
#define KG   256
#define NBLK 128
#define NJ   8
#define NTH  512

typedef unsigned long long u64;
typedef unsigned int u32;

/* Scratch (static device globals; no runtime allocation). */
__device__ float4 g_pre0[(size_t)TT * KG * BB];   /* [t][j4][b] fp32 */
/* h state as split-bf16 planes in MMA-fragment block layout:
   plane u32 index for element (row,col):
     mt=row>>4, q=row&7, rsel=(row>>3)&1, kt=col>>4, kb=(col&7)>>1,
     khigh=(col>>3)&1, klane=col&1
     u32 = [ ((mt*64+kt)*32 + q*4 + kb)*4 + rsel + 2*khigh ], bf16 half = klane.
   A-fragment for warp m-tile mt, k-tile kt, lane l = uint4 at (mt*64+kt)*32 + l. */
__device__ uint4 g_A0[2][2][16384];   /* [parity][hi/lo] layer-0 h */
__device__ uint4 g_A1[2][2][16384];   /* [parity][hi/lo] layer-1 h */
__device__ u32 g_flags[NBLK * 64];

/* ---------------- helpers ---------------- */
__device__ __forceinline__ u64 fma2(u64 a, u64 b, u64 c) {
    u64 d; asm("fma.rn.f32x2 %0, %1, %2, %3;" : "=l"(d) : "l"(a), "l"(b), "l"(c)); return d;
}
__device__ __forceinline__ u64 pack2(float x, float y) {
    u64 r; asm("mov.b64 %0, {%1, %2};" : "=l"(r) : "f"(x), "f"(y)); return r;
}
__device__ __forceinline__ float2 unpk(u64 v) {
    float2 f; asm("mov.b64 {%0, %1}, %2;" : "=f"(f.x), "=f"(f.y) : "l"(v)); return f;
}
__device__ __forceinline__ uint4 ldcg4(const uint4* p) {
    uint4 v;
    asm("ld.global.cg.v4.u32 {%0,%1,%2,%3}, [%4];"
        : "=r"(v.x), "=r"(v.y), "=r"(v.z), "=r"(v.w) : "l"(p));
    return v;
}
__device__ __forceinline__ void mma16816(float* d, uint4 a, uint2 b) {
    asm("mma.sync.aligned.m16n8k16.row.col.f32.bf16.bf16.f32 "
        "{%0,%1,%2,%3}, {%4,%5,%6,%7}, {%8,%9}, {%0,%1,%2,%3};"
        : "+f"(d[0]), "+f"(d[1]), "+f"(d[2]), "+f"(d[3])
        : "r"(a.x), "r"(a.y), "r"(a.z), "r"(a.w), "r"(b.x), "r"(b.y));
}
__device__ __forceinline__ u32 bfpack(float x, float y) {
    unsigned short lx = __bfloat16_as_ushort(__float2bfloat16(x));
    unsigned short ly = __bfloat16_as_ushort(__float2bfloat16(y));
    return (u32)lx | ((u32)ly << 16);
}
__device__ __forceinline__ float bflo(u32 v) { return __bfloat162float(__ushort_as_bfloat16((unsigned short)(v & 0xffff))); }
__device__ __forceinline__ float bfhi(u32 v) { return __bfloat162float(__ushort_as_bfloat16((unsigned short)(v >> 16))); }

/* ------------------------------------------------------------------ */
/* Kernel 1: pre0 GEMM (unchanged from R10) + flag reset.              */
/* ------------------------------------------------------------------ */
__global__ __launch_bounds__(256) void pre_gemm(const float* __restrict__ x,
                                                const float* __restrict__ Wi,
                                                const float* __restrict__ bi)
{
    if (blockIdx.x == 0 && blockIdx.y == 0 && threadIdx.x < NBLK)
        g_flags[threadIdx.x * 64] = 0u;

    __shared__ float  sA[32][129];
    __shared__ float4 sB[32 * 16];

    const int t     = blockIdx.y;
    const int jbase = blockIdx.x * 64;
    const int tid   = threadIdx.x;
    const int rid   = tid & 31;
    const int cid   = tid >> 5;

    u64 acc[4][4];
#pragma unroll
    for (int i = 0; i < 4; ++i)
#pragma unroll
        for (int j = 0; j < 4; ++j) acc[i][j] = 0ull;

    const int brow = tid >> 1;
    const int half = tid & 1;

    for (int k0 = 0; k0 < HH; k0 += 32) {
        __syncthreads();
        const float* xs = x + ((size_t)brow * TT + t) * HH + k0 + half * 16;
#pragma unroll
        for (int q = 0; q < 4; ++q) {
            float4 v = *(const float4*)(xs + 4 * q);
            int kk = half * 16 + 4 * q;
            sA[kk + 0][brow] = v.x; sA[kk + 1][brow] = v.y;
            sA[kk + 2][brow] = v.z; sA[kk + 3][brow] = v.w;
        }
#pragma unroll
        for (int q = 0; q < 2; ++q) {
            int idx = tid + 256 * q;
            int kk = idx >> 4, jf = idx & 15;
            sB[idx] = *(const float4*)(Wi + (size_t)(k0 + kk) * HH + jbase + 4 * jf);
        }
        __syncthreads();

#pragma unroll
        for (int kk = 0; kk < 32; ++kk) {
            float a0 = sA[kk][rid], a1 = sA[kk][rid + 32];
            float a2 = sA[kk][rid + 64], a3 = sA[kk][rid + 96];
            const ulonglong2* bp = (const ulonglong2*)&sB[kk * 16 + cid * 2];
            ulonglong2 bb0 = bp[0];
            ulonglong2 bb1 = bp[1];
            u64 ad0 = pack2(a0, a0), ad1 = pack2(a1, a1);
            u64 ad2 = pack2(a2, a2), ad3 = pack2(a3, a3);
            acc[0][0] = fma2(ad0, bb0.x, acc[0][0]); acc[0][1] = fma2(ad0, bb0.y, acc[0][1]);
            acc[0][2] = fma2(ad0, bb1.x, acc[0][2]); acc[0][3] = fma2(ad0, bb1.y, acc[0][3]);
            acc[1][0] = fma2(ad1, bb0.x, acc[1][0]); acc[1][1] = fma2(ad1, bb0.y, acc[1][1]);
            acc[1][2] = fma2(ad1, bb1.x, acc[1][2]); acc[1][3] = fma2(ad1, bb1.y, acc[1][3]);
            acc[2][0] = fma2(ad2, bb0.x, acc[2][0]); acc[2][1] = fma2(ad2, bb0.y, acc[2][1]);
            acc[2][2] = fma2(ad2, bb1.x, acc[2][2]); acc[2][3] = fma2(ad2, bb1.y, acc[2][3]);
            acc[3][0] = fma2(ad3, bb0.x, acc[3][0]); acc[3][1] = fma2(ad3, bb0.y, acc[3][1]);
            acc[3][2] = fma2(ad3, bb1.x, acc[3][2]); acc[3][3] = fma2(ad3, bb1.y, acc[3][3]);
        }
    }

    float biv[8];
#pragma unroll
    for (int j = 0; j < 8; ++j) biv[j] = __ldg(&bi[jbase + cid * 8 + j]);

    const int jg = (jbase + cid * 8) >> 2;
#pragma unroll
    for (int i = 0; i < 4; ++i) {
        int row = rid + 32 * i;
#pragma unroll
        for (int gq = 0; gq < 2; ++gq) {
            float2 u0 = unpk(acc[i][2 * gq]);
            float2 u1 = unpk(acc[i][2 * gq + 1]);
            float4 v;
            v.x = u0.x + biv[4 * gq + 0];
            v.y = u0.y + biv[4 * gq + 1];
            v.z = u1.x + biv[4 * gq + 2];
            v.w = u1.y + biv[4 * gq + 3];
            g_pre0[((size_t)t * KG + jg + gq) * BB + row] = v;
        }
    }
}

/* ---------------- distributed grid barrier (R9) ---------------- */
__device__ __forceinline__ void grid_arrive(int cta, int th, u32 ph)
{
    __syncthreads();
    if (th == 0) {
        asm volatile("st.release.gpu.global.u32 [%0], %1;"
                     :: "l"(&g_flags[cta * 64]), "r"(ph) : "memory");
    }
}
__device__ __forceinline__ void grid_wait(int th, u32 ph)
{
    if (th < NBLK) {
        u32 v;
        do {
            asm volatile("ld.acquire.gpu.global.u32 %0, [%1];"
                         : "=r"(v) : "l"(&g_flags[th * 64]) : "memory");
        } while (v < ph);
    }
    __syncthreads();
}

/* MMA compute for one k-tile: 12 mma (4 products x 3 matrices). */
#define COMPUTE_KT(a0h, a0l, a1h, a1l, KT)                                   \
    {                                                                        \
        int kt_ = (KT);                                                      \
        uint2 w0h = sB2[0 * 2048 + kt_ * 32 + lane];                         \
        uint2 w0l = sB2[1 * 2048 + kt_ * 32 + lane];                         \
        uint2 w1h = sB2[2 * 2048 + kt_ * 32 + lane];                         \
        uint2 w1l = sB2[3 * 2048 + kt_ * 32 + lane];                         \
        uint2 w2h = sB2[4 * 2048 + kt_ * 32 + lane];                         \
        uint2 w2l = sB2[5 * 2048 + kt_ * 32 + lane];                         \
        mma16816(acc1a, a0h, w0h);                                           \
        mma16816(acc1b, a1h, w1h);                                           \
        mma16816(acc0,  a0h, w2h);                                           \
        mma16816(acc1a, a0h, w0l);                                           \
        mma16816(acc1b, a1h, w1l);                                           \
        mma16816(acc0,  a0h, w2l);                                           \
        mma16816(acc1a, a0l, w0h);                                           \
        mma16816(acc1b, a1l, w1h);                                           \
        mma16816(acc0,  a0l, w2h);                                           \
        mma16816(acc1a, a0l, w0l);                                           \
        mma16816(acc1b, a1l, w1l);                                           \
        mma16816(acc0,  a0l, w2l);                                           \
    }

#define LOADA(a0h, a0l, a1h, a1l, KT)                                        \
    {                                                                        \
        int fo_ = (mt * 64 + (KT)) * 32 + lane;                              \
        a0h = ldcg4(pA0h + fo_);  a0l = ldcg4(pA0l + fo_);                   \
        a1h = ldcg4(pA1h + fo_);  a1l = ldcg4(pA1l + fo_);                   \
    }

/* ------------------------------------------------------------------ */
/* Kernel 2: persistent RNN on tensor cores (mma.sync bf16-split).     */
/* 128 CTAs x 512 thr; warp = (m-tile 0..7, K-half 0..1).              */
/* ------------------------------------------------------------------ */
__global__ __launch_bounds__(NTH, 1) void rnn_persist(const float* __restrict__ h0,
                                                      const float* __restrict__ Wi,
                                                      const float* __restrict__ bi,
                                                      const float* __restrict__ Wh,
                                                      const float* __restrict__ bh,
                                                      float* __restrict__ out)
{
    extern __shared__ u32 smemU[];
    u32*   sBu = smemU;                       /* 24576 u32 = 96KB weight frags */
    const uint2* sB2 = (const uint2*)smemU;
    float* sr  = (float*)(smemU + 24576);     /* sr1: [2][8][130] = 2080 f; sr0 after */
    float* sr0 = sr + 2080;                   /* total 4160 floats */

    const int cta  = blockIdx.x;
    const int th   = threadIdx.x;
    const int wid  = th >> 5;
    const int lane = th & 31;
    const int mt   = wid & 7;
    const int kh   = wid >> 3;
    const int j0   = cta * NJ;

    /* final-pass / writer mapping: thread -> (frow, cols c0,c0+1) */
    const int frow = th >> 2;
    const int c0   = (th & 3) * 2;
    const int fjg4 = (j0 + c0) >> 2;
    const int fcl  = c0 & 3;
    const int colg = j0 + c0;
    const int wmt  = frow >> 4, wq = frow & 7, wrsel = (frow >> 3) & 1;
    const int wkt  = colg >> 4, wkb = (colg & 7) >> 1, wkhigh = (colg >> 3) & 1;
    const int wadd = (((wmt * 64 + wkt) * 32) + wq * 4 + wkb) * 4 + wrsel + 2 * wkhigh;

    const float* Wi1g = Wi + (size_t)HH * HH;
    const float* Wh1g = Wh + (size_t)HH * HH;

    /* ---- one-time: pack weights into bf16 hi/lo MMA fragments ----
       sBu[idx], idx = ms*4096 + kt*64 + l*2 + r;
       ms: 0=Wi1 hi,1=Wi1 lo,2=Wh1 hi,3=Wh1 lo,4=Wh0 hi,5=Wh0 lo.
       B frag (col-major): reg r: k = kt*16 + (l&3)*2 + r*8 + {0,1}, n = l>>2. */
    for (int idx = th; idx < 24576; idx += NTH) {
        int ms = idx >> 12;
        int m  = ms >> 1, s = ms & 1;
        int rem = idx & 4095;
        int kt = rem >> 6, lr = rem & 63;
        int l  = lr >> 1, r = lr & 1;
        int n  = l >> 2;
        int k0 = kt * 16 + (l & 3) * 2 + r * 8;
        const float* M = (m == 0) ? Wi1g : (m == 1) ? Wh1g : Wh;
        float w0 = M[(size_t)k0 * HH + j0 + n];
        float w1 = M[(size_t)(k0 + 1) * HH + j0 + n];
        if (s == 1) {
            w0 = w0 - __bfloat162float(__float2bfloat16(w0));
            w1 = w1 - __bfloat162float(__float2bfloat16(w1));
        }
        sBu[idx] = bfpack(w0, w1);
    }

    const float bs1_0 = __ldg(&bi[HH + colg])     + __ldg(&bh[HH + colg]);
    const float bs1_1 = __ldg(&bi[HH + colg + 1]) + __ldg(&bh[HH + colg + 1]);
    const float b0r_0 = __ldg(&bh[colg]);
    const float b0r_1 = __ldg(&bh[colg + 1]);

    /* h1 init -> A1 planes parity 1 (this CTA's cols, all rows; broadcast). */
    {
        float y0 = h0[HH + colg], y1 = h0[HH + colg + 1];
        float h0f = __bfloat162float(__float2bfloat16(y0));
        float h1f = __bfloat162float(__float2bfloat16(y1));
        ((u32*)g_A1[1][0])[wadd] = bfpack(y0, y1);
        ((u32*)g_A1[1][1])[wadd] = bfpack(y0 - h0f, y1 - h1f);
    }
    __syncthreads();   /* weight frags ready */

    /* hn0[0] init: dot0[col] = h0_l0 @ Wh0 via split-bf16 frags. */
    {
        int icol = th >> 6, ipart = th & 63;   /* kt = ipart */
        float dot = 0.0f;
        for (int e = 0; e < 16; ++e) {
            int k = ipart * 16 + e;
            int l = icol * 4 + ((k & 7) >> 1);
            int r = (k >> 3) & 1;
            u32 vh = sBu[4 * 4096 + ipart * 64 + l * 2 + r];
            u32 vl = sBu[5 * 4096 + ipart * 64 + l * 2 + r];
            float w = ((k & 1) ? bfhi(vh) : bflo(vh)) + ((k & 1) ? bfhi(vl) : bflo(vl));
            dot = fmaf(w, h0[k], dot);
        }
        sr[icol * 64 + ipart] = dot;
    }
    __syncthreads();
    {
        float dv0 = 0.0f, dv1 = 0.0f;
#pragma unroll 8
        for (int p = 0; p < 64; ++p) {
            dv0 += sr[c0 * 64 + p];
            dv1 += sr[(c0 + 1) * 64 + p];
        }
        const float* preF = (const float*)g_pre0;
        float p0v = preF[((size_t)fjg4 * BB + frow) * 4 + fcl];
        float p1v = preF[((size_t)fjg4 * BB + frow) * 4 + fcl + 1];
        float y0 = tanhf(p0v + dv0 + b0r_0);
        float y1 = tanhf(p1v + dv1 + b0r_1);
        float h0f = __bfloat162float(__float2bfloat16(y0));
        float h1f = __bfloat162float(__float2bfloat16(y1));
        ((u32*)g_A0[0][0])[wadd] = bfpack(y0, y1);
        ((u32*)g_A0[0][1])[wadd] = bfpack(y0 - h0f, y1 - h1f);
    }

    u32 ph = 1;
    grid_arrive(cta, th, ph);
    grid_wait(th, ph);
    ++ph;

    const int rrow = mt * 16 + (lane >> 2);     /* D frag row (and +8) */
    const int ccol = (lane & 3) * 2;            /* D frag cols (and +1) */

    for (int t = 0; t < TT; ++t) {
        const uint4* pA0h = g_A0[t & 1][0];
        const uint4* pA0l = g_A0[t & 1][1];
        const uint4* pA1h = g_A1[(t + 1) & 1][0];
        const uint4* pA1l = g_A1[(t + 1) & 1][1];

        /* hoisted pre0[t+1] prefetch */
        float2 pn = make_float2(0.0f, 0.0f);
        if (t < TT - 1) {
            const float* pp = (const float*)g_pre0 +
                ((size_t)((size_t)(t + 1) * KG + fjg4) * BB + frow) * 4 + fcl;
            asm("ld.global.cg.v2.f32 {%0,%1}, [%2];" : "=f"(pn.x), "=f"(pn.y) : "l"(pp));
        }

        float acc1a[4] = {0, 0, 0, 0};
        float acc1b[4] = {0, 0, 0, 0};
        float acc0[4]  = {0, 0, 0, 0};

        {
            const int ktb = kh * 32;
            uint4 Xa0h, Xa0l, Xa1h, Xa1l, Ya0h, Ya0l, Ya1h, Ya1l;
            LOADA(Xa0h, Xa0l, Xa1h, Xa1l, ktb);
#pragma unroll 1
            for (int i = 0; i < 32; i += 2) {
                LOADA(Ya0h, Ya0l, Ya1h, Ya1l, ktb + i + 1);
                COMPUTE_KT(Xa0h, Xa0l, Xa1h, Xa1l, ktb + i);
                if (i + 2 < 32) { LOADA(Xa0h, Xa0l, Xa1h, Xa1l, ktb + i + 2); }
                COMPUTE_KT(Ya0h, Ya0l, Ya1h, Ya1l, ktb + i + 1);
            }
        }

        /* write partials: sr1/sr0 [kh][col][row(130)] */
        {
            float s1r[4];
#pragma unroll
            for (int r = 0; r < 4; ++r) s1r[r] = acc1a[r] + acc1b[r];
            int b1 = (kh * 8 + ccol) * 130;
            sr [b1 + rrow]           = s1r[0];
            sr [b1 + 130 + rrow]     = s1r[1];
            sr [b1 + rrow + 8]       = s1r[2];
            sr [b1 + 130 + rrow + 8] = s1r[3];
            sr0[b1 + rrow]           = acc0[0];
            sr0[b1 + 130 + rrow]     = acc0[1];
            sr0[b1 + rrow + 8]       = acc0[2];
            sr0[b1 + 130 + rrow + 8] = acc0[3];
        }
        __syncthreads();

        /* final pass: (frow, c0..c0+1) */
        {
            float s1_0 = sr[(0 * 8 + c0) * 130 + frow]       + sr[(1 * 8 + c0) * 130 + frow];
            float s1_1 = sr[(0 * 8 + c0 + 1) * 130 + frow]   + sr[(1 * 8 + c0 + 1) * 130 + frow];
            float y0 = tanhf(s1_0 + bs1_0);
            float y1 = tanhf(s1_1 + bs1_1);

            /* publish h1[t] (split) */
            float h0f = __bfloat162float(__float2bfloat16(y0));
            float h1f = __bfloat162float(__float2bfloat16(y1));
            ((u32*)g_A1[t & 1][0])[wadd] = bfpack(y0, y1);
            ((u32*)g_A1[t & 1][1])[wadd] = bfpack(y0 - h0f, y1 - h1f);

            if (t < TT - 1) {
                float s0_0 = sr0[(0 * 8 + c0) * 130 + frow]     + sr0[(1 * 8 + c0) * 130 + frow];
                float s0_1 = sr0[(0 * 8 + c0 + 1) * 130 + frow] + sr0[(1 * 8 + c0 + 1) * 130 + frow];
                float z0 = tanhf(s0_0 + pn.x + b0r_0);
                float z1 = tanhf(s0_1 + pn.y + b0r_1);
                float z0f = __bfloat162float(__float2bfloat16(z0));
                float z1f = __bfloat162float(__float2bfloat16(z1));
                ((u32*)g_A0[(t + 1) & 1][0])[wadd] = bfpack(z0, z1);
                ((u32*)g_A0[(t + 1) & 1][1])[wadd] = bfpack(z0 - z0f, z1 - z1f);

                grid_arrive(cta, th, ph);
                out[((size_t)frow * TT + t) * HH + colg]     = y0;
                out[((size_t)frow * TT + t) * HH + colg + 1] = y1;
                grid_wait(th, ph);
                ++ph;
            } else {
                out[((size_t)frow * TT + t) * HH + colg]     = y0;
                out[((size_t)frow * TT + t) * HH + colg + 1] = y1;
                float* hn = out + (size_t)BB * TT * HH;
                hn[(size_t)(frow * 2 + 1) * HH + colg]     = y0;
                hn[(size_t)(frow * 2 + 1) * HH + colg + 1] = y1;
                u32 vh = ((const u32*)g_A0[t & 1][0])[wadd];
                u32 vl = ((const u32*)g_A0[t & 1][1])[wadd];
                hn[(size_t)(frow * 2) * HH + colg]     = bflo(vh) + bflo(vl);
                hn[(size_t)(frow * 2) * HH + colg + 1] = bfhi(vh) + bfhi(vl);
            }
        }
    }
}

/* ------------------------------------------------------------------ */
extern "C" void kernel_launch(void* const* d_in, const int* in_sizes, int n_in,
                              void* d_out, int out_size)
{
    const float* x  = (const float*)d_in[0];
    const float* h0 = (const float*)d_in[1];
    const float* Wi = (const float*)d_in[2];
    const float* bi = (const float*)d_in[3];
    const float* Wh = (const float*)d_in[4];
    const float* bh = (const float*)d_in[5];
    float* out = (float*)d_out;

    dim3 g2(16, 256);
    pre_gemm<<<g2, 256>>>(x, Wi, bi);

    size_t smem = 24576 * sizeof(u32) + 4160 * sizeof(float);   /* ~112.6 KB */
    cudaFuncSetAttribute(rnn_persist, cudaFuncAttributeMaxDynamicSharedMemorySize, (int)smem);
    rnn_persist<<<NBLK, NTH, smem>>>(h0, Wi, bi, Wh, bh, out);
}

// round 12
// speedup vs baseline: 2.3256x; 1.0046x over previous
#include <cuda_runtime.h>
#include <cuda_bf16.h>
#include <math.h>

#define BB   128
#define TT   256
#define HH   1024
#define KG   256
#define NBLK 128
#define NJ   8
#define NTH  512

typedef unsigned long long u64;
typedef unsigned int u32;

/* Scratch (static device globals; no runtime allocation). */
__device__ float4 g_pre0[(size_t)TT * KG * BB];   /* [t][j4][b] fp32 */
/* h state as split-bf16 planes in MMA-fragment block layout (see R11). */
__device__ uint4 g_A0[2][2][16384];   /* [parity][hi/lo] layer-0 h */
__device__ uint4 g_A1[2][2][16384];   /* [parity][hi/lo] layer-1 h */
__device__ u32 g_flags[NBLK * 64];

/* ---------------- helpers ---------------- */
__device__ __forceinline__ u64 fma2(u64 a, u64 b, u64 c) {
    u64 d; asm("fma.rn.f32x2 %0, %1, %2, %3;" : "=l"(d) : "l"(a), "l"(b), "l"(c)); return d;
}
__device__ __forceinline__ u64 pack2(float x, float y) {
    u64 r; asm("mov.b64 %0, {%1, %2};" : "=l"(r) : "f"(x), "f"(y)); return r;
}
__device__ __forceinline__ float2 unpk(u64 v) {
    float2 f; asm("mov.b64 {%0, %1}, %2;" : "=f"(f.x), "=f"(f.y) : "l"(v)); return f;
}
__device__ __forceinline__ uint4 ldcg4(const uint4* p) {
    uint4 v;
    asm("ld.global.cg.v4.u32 {%0,%1,%2,%3}, [%4];"
        : "=r"(v.x), "=r"(v.y), "=r"(v.z), "=r"(v.w) : "l"(p));
    return v;
}
__device__ __forceinline__ void mma16816(float* d, uint4 a, uint2 b) {
    asm("mma.sync.aligned.m16n8k16.row.col.f32.bf16.bf16.f32 "
        "{%0,%1,%2,%3}, {%4,%5,%6,%7}, {%8,%9}, {%0,%1,%2,%3};"
        : "+f"(d[0]), "+f"(d[1]), "+f"(d[2]), "+f"(d[3])
        : "r"(a.x), "r"(a.y), "r"(a.z), "r"(a.w), "r"(b.x), "r"(b.y));
}
__device__ __forceinline__ u32 bfpack(float x, float y) {
    unsigned short lx = __bfloat16_as_ushort(__float2bfloat16(x));
    unsigned short ly = __bfloat16_as_ushort(__float2bfloat16(y));
    return (u32)lx | ((u32)ly << 16);
}
__device__ __forceinline__ float bflo(u32 v) { return __bfloat162float(__ushort_as_bfloat16((unsigned short)(v & 0xffff))); }
__device__ __forceinline__ float bfhi(u32 v) { return __bfloat162float(__ushort_as_bfloat16((unsigned short)(v >> 16))); }

/* ------------------------------------------------------------------ */
/* Kernel 1: pre0 GEMM (unchanged) + flag reset.                       */
/* ------------------------------------------------------------------ */
__global__ __launch_bounds__(256) void pre_gemm(const float* __restrict__ x,
                                                const float* __restrict__ Wi,
                                                const float* __restrict__ bi)
{
    if (blockIdx.x == 0 && blockIdx.y == 0 && threadIdx.x < NBLK)
        g_flags[threadIdx.x * 64] = 0u;

    __shared__ float  sA[32][129];
    __shared__ float4 sB[32 * 16];

    const int t     = blockIdx.y;
    const int jbase = blockIdx.x * 64;
    const int tid   = threadIdx.x;
    const int rid   = tid & 31;
    const int cid   = tid >> 5;

    u64 acc[4][4];
#pragma unroll
    for (int i = 0; i < 4; ++i)
#pragma unroll
        for (int j = 0; j < 4; ++j) acc[i][j] = 0ull;

    const int brow = tid >> 1;
    const int half = tid & 1;

    for (int k0 = 0; k0 < HH; k0 += 32) {
        __syncthreads();
        const float* xs = x + ((size_t)brow * TT + t) * HH + k0 + half * 16;
#pragma unroll
        for (int q = 0; q < 4; ++q) {
            float4 v = *(const float4*)(xs + 4 * q);
            int kk = half * 16 + 4 * q;
            sA[kk + 0][brow] = v.x; sA[kk + 1][brow] = v.y;
            sA[kk + 2][brow] = v.z; sA[kk + 3][brow] = v.w;
        }
#pragma unroll
        for (int q = 0; q < 2; ++q) {
            int idx = tid + 256 * q;
            int kk = idx >> 4, jf = idx & 15;
            sB[idx] = *(const float4*)(Wi + (size_t)(k0 + kk) * HH + jbase + 4 * jf);
        }
        __syncthreads();

#pragma unroll
        for (int kk = 0; kk < 32; ++kk) {
            float a0 = sA[kk][rid], a1 = sA[kk][rid + 32];
            float a2 = sA[kk][rid + 64], a3 = sA[kk][rid + 96];
            const ulonglong2* bp = (const ulonglong2*)&sB[kk * 16 + cid * 2];
            ulonglong2 bb0 = bp[0];
            ulonglong2 bb1 = bp[1];
            u64 ad0 = pack2(a0, a0), ad1 = pack2(a1, a1);
            u64 ad2 = pack2(a2, a2), ad3 = pack2(a3, a3);
            acc[0][0] = fma2(ad0, bb0.x, acc[0][0]); acc[0][1] = fma2(ad0, bb0.y, acc[0][1]);
            acc[0][2] = fma2(ad0, bb1.x, acc[0][2]); acc[0][3] = fma2(ad0, bb1.y, acc[0][3]);
            acc[1][0] = fma2(ad1, bb0.x, acc[1][0]); acc[1][1] = fma2(ad1, bb0.y, acc[1][1]);
            acc[1][2] = fma2(ad1, bb1.x, acc[1][2]); acc[1][3] = fma2(ad1, bb1.y, acc[1][3]);
            acc[2][0] = fma2(ad2, bb0.x, acc[2][0]); acc[2][1] = fma2(ad2, bb0.y, acc[2][1]);
            acc[2][2] = fma2(ad2, bb1.x, acc[2][2]); acc[2][3] = fma2(ad2, bb1.y, acc[2][3]);
            acc[3][0] = fma2(ad3, bb0.x, acc[3][0]); acc[3][1] = fma2(ad3, bb0.y, acc[3][1]);
            acc[3][2] = fma2(ad3, bb1.x, acc[3][2]); acc[3][3] = fma2(ad3, bb1.y, acc[3][3]);
        }
    }

    float biv[8];
#pragma unroll
    for (int j = 0; j < 8; ++j) biv[j] = __ldg(&bi[jbase + cid * 8 + j]);

    const int jg = (jbase + cid * 8) >> 2;
#pragma unroll
    for (int i = 0; i < 4; ++i) {
        int row = rid + 32 * i;
#pragma unroll
        for (int gq = 0; gq < 2; ++gq) {
            float2 u0 = unpk(acc[i][2 * gq]);
            float2 u1 = unpk(acc[i][2 * gq + 1]);
            float4 v;
            v.x = u0.x + biv[4 * gq + 0];
            v.y = u0.y + biv[4 * gq + 1];
            v.z = u1.x + biv[4 * gq + 2];
            v.w = u1.y + biv[4 * gq + 3];
            g_pre0[((size_t)t * KG + jg + gq) * BB + row] = v;
        }
    }
}

/* ---------------- distributed grid barrier ---------------- */
__device__ __forceinline__ void grid_arrive(int cta, int th, u32 ph)
{
    __syncthreads();
    if (th == 0) {
        asm volatile("st.release.gpu.global.u32 [%0], %1;"
                     :: "l"(&g_flags[cta * 64]), "r"(ph) : "memory");
    }
}
__device__ __forceinline__ void grid_wait(int th, u32 ph)
{
    if (th < NBLK) {
        u32 v;
        do {
            asm volatile("ld.acquire.gpu.global.u32 %0, [%1];"
                         : "=r"(v) : "l"(&g_flags[th * 64]) : "memory");
        } while (v < ph);
    }
    __syncthreads();
}

/* MMA compute for one k-tile: 9 mma (3 products x 3 matrices),
   6 independent accumulator chains for ILP. lo*lo dropped (O(2^-18)). */
#define COMPUTE_KT(a0h, a0l, a1h, a1l, KT)                                   \
    {                                                                        \
        int kt_ = (KT);                                                      \
        uint2 w0h = sB2[0 * 2048 + kt_ * 32 + lane];                         \
        uint2 w0l = sB2[1 * 2048 + kt_ * 32 + lane];                         \
        uint2 w1h = sB2[2 * 2048 + kt_ * 32 + lane];                         \
        uint2 w1l = sB2[3 * 2048 + kt_ * 32 + lane];                         \
        uint2 w2h = sB2[4 * 2048 + kt_ * 32 + lane];                         \
        uint2 w2l = sB2[5 * 2048 + kt_ * 32 + lane];                         \
        mma16816(acc1a,  a0h, w0h);                                          \
        mma16816(acc1b,  a1h, w1h);                                          \
        mma16816(acc0,   a0h, w2h);                                          \
        mma16816(acc1a2, a0h, w0l);                                          \
        mma16816(acc1b2, a1h, w1l);                                          \
        mma16816(acc0b,  a0h, w2l);                                          \
        mma16816(acc1a2, a0l, w0h);                                          \
        mma16816(acc1b2, a1l, w1h);                                          \
        mma16816(acc0b,  a0l, w2h);                                          \
    }

#define LOADA(a0h, a0l, a1h, a1l, KT)                                        \
    {                                                                        \
        int fo_ = (mt * 64 + (KT)) * 32 + lane;                              \
        a0h = ldcg4(pA0h + fo_);  a0l = ldcg4(pA0l + fo_);                   \
        a1h = ldcg4(pA1h + fo_);  a1l = ldcg4(pA1l + fo_);                   \
    }

/* ------------------------------------------------------------------ */
/* Kernel 2: persistent RNN on tensor cores (mma.sync bf16-split).     */
/* ------------------------------------------------------------------ */
__global__ __launch_bounds__(NTH, 1) void rnn_persist(const float* __restrict__ h0,
                                                      const float* __restrict__ Wi,
                                                      const float* __restrict__ bi,
                                                      const float* __restrict__ Wh,
                                                      const float* __restrict__ bh,
                                                      float* __restrict__ out)
{
    extern __shared__ u32 smemU[];
    u32*   sBu = smemU;                       /* 24576 u32 = 96KB weight frags */
    const uint2* sB2 = (const uint2*)smemU;
    float* sr  = (float*)(smemU + 24576);     /* sr1: [2][8][130]; sr0 after */
    float* sr0 = sr + 2080;

    const int cta  = blockIdx.x;
    const int th   = threadIdx.x;
    const int wid  = th >> 5;
    const int lane = th & 31;
    const int mt   = wid & 7;
    const int kh   = wid >> 3;
    const int j0   = cta * NJ;

    const int frow = th >> 2;
    const int c0   = (th & 3) * 2;
    const int fjg4 = (j0 + c0) >> 2;
    const int fcl  = c0 & 3;
    const int colg = j0 + c0;
    const int wmt  = frow >> 4, wq = frow & 7, wrsel = (frow >> 3) & 1;
    const int wkt  = colg >> 4, wkb = (colg & 7) >> 1, wkhigh = (colg >> 3) & 1;
    const int wadd = (((wmt * 64 + wkt) * 32) + wq * 4 + wkb) * 4 + wrsel + 2 * wkhigh;

    const float* Wi1g = Wi + (size_t)HH * HH;
    const float* Wh1g = Wh + (size_t)HH * HH;

    /* one-time: pack weights into bf16 hi/lo MMA fragments (see R11). */
    for (int idx = th; idx < 24576; idx += NTH) {
        int ms = idx >> 12;
        int m  = ms >> 1, s = ms & 1;
        int rem = idx & 4095;
        int kt = rem >> 6, lr = rem & 63;
        int l  = lr >> 1, r = lr & 1;
        int n  = l >> 2;
        int k0 = kt * 16 + (l & 3) * 2 + r * 8;
        const float* M = (m == 0) ? Wi1g : (m == 1) ? Wh1g : Wh;
        float w0 = M[(size_t)k0 * HH + j0 + n];
        float w1 = M[(size_t)(k0 + 1) * HH + j0 + n];
        if (s == 1) {
            w0 = w0 - __bfloat162float(__float2bfloat16(w0));
            w1 = w1 - __bfloat162float(__float2bfloat16(w1));
        }
        sBu[idx] = bfpack(w0, w1);
    }

    const float bs1_0 = __ldg(&bi[HH + colg])     + __ldg(&bh[HH + colg]);
    const float bs1_1 = __ldg(&bi[HH + colg + 1]) + __ldg(&bh[HH + colg + 1]);
    const float b0r_0 = __ldg(&bh[colg]);
    const float b0r_1 = __ldg(&bh[colg + 1]);

    /* h1 init -> A1 planes parity 1. */
    {
        float y0 = h0[HH + colg], y1 = h0[HH + colg + 1];
        float h0f = __bfloat162float(__float2bfloat16(y0));
        float h1f = __bfloat162float(__float2bfloat16(y1));
        ((u32*)g_A1[1][0])[wadd] = bfpack(y0, y1);
        ((u32*)g_A1[1][1])[wadd] = bfpack(y0 - h0f, y1 - h1f);
    }
    __syncthreads();

    /* hn0[0] init: dot0[col] = h0_l0 @ Wh0 via split-bf16 frags. */
    {
        int icol = th >> 6, ipart = th & 63;
        float dot = 0.0f;
        for (int e = 0; e < 16; ++e) {
            int k = ipart * 16 + e;
            int l = icol * 4 + ((k & 7) >> 1);
            int r = (k >> 3) & 1;
            u32 vh = sBu[4 * 4096 + ipart * 64 + l * 2 + r];
            u32 vl = sBu[5 * 4096 + ipart * 64 + l * 2 + r];
            float w = ((k & 1) ? bfhi(vh) : bflo(vh)) + ((k & 1) ? bfhi(vl) : bflo(vl));
            dot = fmaf(w, h0[k], dot);
        }
        sr[icol * 64 + ipart] = dot;
    }
    __syncthreads();
    {
        float dv0 = 0.0f, dv1 = 0.0f;
#pragma unroll 8
        for (int p = 0; p < 64; ++p) {
            dv0 += sr[c0 * 64 + p];
            dv1 += sr[(c0 + 1) * 64 + p];
        }
        const float* preF = (const float*)g_pre0;
        float p0v = preF[((size_t)fjg4 * BB + frow) * 4 + fcl];
        float p1v = preF[((size_t)fjg4 * BB + frow) * 4 + fcl + 1];
        float y0 = tanhf(p0v + dv0 + b0r_0);
        float y1 = tanhf(p1v + dv1 + b0r_1);
        float h0f = __bfloat162float(__float2bfloat16(y0));
        float h1f = __bfloat162float(__float2bfloat16(y1));
        ((u32*)g_A0[0][0])[wadd] = bfpack(y0, y1);
        ((u32*)g_A0[0][1])[wadd] = bfpack(y0 - h0f, y1 - h1f);
    }

    u32 ph = 1;
    grid_arrive(cta, th, ph);
    grid_wait(th, ph);
    ++ph;

    const int rrow = mt * 16 + (lane >> 2);
    const int ccol = (lane & 3) * 2;

    for (int t = 0; t < TT; ++t) {
        const uint4* pA0h = g_A0[t & 1][0];
        const uint4* pA0l = g_A0[t & 1][1];
        const uint4* pA1h = g_A1[(t + 1) & 1][0];
        const uint4* pA1l = g_A1[(t + 1) & 1][1];

        float2 pn = make_float2(0.0f, 0.0f);
        if (t < TT - 1) {
            const float* pp = (const float*)g_pre0 +
                ((size_t)((size_t)(t + 1) * KG + fjg4) * BB + frow) * 4 + fcl;
            asm("ld.global.cg.v2.f32 {%0,%1}, [%2];" : "=f"(pn.x), "=f"(pn.y) : "l"(pp));
        }

        float acc1a[4]  = {0, 0, 0, 0};
        float acc1a2[4] = {0, 0, 0, 0};
        float acc1b[4]  = {0, 0, 0, 0};
        float acc1b2[4] = {0, 0, 0, 0};
        float acc0[4]   = {0, 0, 0, 0};
        float acc0b[4]  = {0, 0, 0, 0};

        {
            const int ktb = kh * 32;
            uint4 Xa0h, Xa0l, Xa1h, Xa1l, Ya0h, Ya0l, Ya1h, Ya1l;
            LOADA(Xa0h, Xa0l, Xa1h, Xa1l, ktb);
#pragma unroll 1
            for (int i = 0; i < 32; i += 2) {
                LOADA(Ya0h, Ya0l, Ya1h, Ya1l, ktb + i + 1);
                COMPUTE_KT(Xa0h, Xa0l, Xa1h, Xa1l, ktb + i);
                if (i + 2 < 32) { LOADA(Xa0h, Xa0l, Xa1h, Xa1l, ktb + i + 2); }
                COMPUTE_KT(Ya0h, Ya0l, Ya1h, Ya1l, ktb + i + 1);
            }
        }

        /* write partials: sr1/sr0 [kh][col][row(130)] */
        {
            int b1 = (kh * 8 + ccol) * 130;
            sr [b1 + rrow]           = acc1a[0] + acc1a2[0] + acc1b[0] + acc1b2[0];
            sr [b1 + 130 + rrow]     = acc1a[1] + acc1a2[1] + acc1b[1] + acc1b2[1];
            sr [b1 + rrow + 8]       = acc1a[2] + acc1a2[2] + acc1b[2] + acc1b2[2];
            sr [b1 + 130 + rrow + 8] = acc1a[3] + acc1a2[3] + acc1b[3] + acc1b2[3];
            sr0[b1 + rrow]           = acc0[0] + acc0b[0];
            sr0[b1 + 130 + rrow]     = acc0[1] + acc0b[1];
            sr0[b1 + rrow + 8]       = acc0[2] + acc0b[2];
            sr0[b1 + 130 + rrow + 8] = acc0[3] + acc0b[3];
        }
        __syncthreads();

        /* final pass: (frow, c0..c0+1) */
        {
            float s1_0 = sr[(0 * 8 + c0) * 130 + frow]       + sr[(1 * 8 + c0) * 130 + frow];
            float s1_1 = sr[(0 * 8 + c0 + 1) * 130 + frow]   + sr[(1 * 8 + c0 + 1) * 130 + frow];
            float y0 = tanhf(s1_0 + bs1_0);
            float y1 = tanhf(s1_1 + bs1_1);

            float h0f = __bfloat162float(__float2bfloat16(y0));
            float h1f = __bfloat162float(__float2bfloat16(y1));
            ((u32*)g_A1[t & 1][0])[wadd] = bfpack(y0, y1);
            ((u32*)g_A1[t & 1][1])[wadd] = bfpack(y0 - h0f, y1 - h1f);

            if (t < TT - 1) {
                float s0_0 = sr0[(0 * 8 + c0) * 130 + frow]     + sr0[(1 * 8 + c0) * 130 + frow];
                float s0_1 = sr0[(0 * 8 + c0 + 1) * 130 + frow] + sr0[(1 * 8 + c0 + 1) * 130 + frow];
                float z0 = tanhf(s0_0 + pn.x + b0r_0);
                float z1 = tanhf(s0_1 + pn.y + b0r_1);
                float z0f = __bfloat162float(__float2bfloat16(z0));
                float z1f = __bfloat162float(__float2bfloat16(z1));
                ((u32*)g_A0[(t + 1) & 1][0])[wadd] = bfpack(z0, z1);
                ((u32*)g_A0[(t + 1) & 1][1])[wadd] = bfpack(z0 - z0f, z1 - z1f);

                grid_arrive(cta, th, ph);
                out[((size_t)frow * TT + t) * HH + colg]     = y0;
                out[((size_t)frow * TT + t) * HH + colg + 1] = y1;
                grid_wait(th, ph);
                ++ph;
            } else {
                out[((size_t)frow * TT + t) * HH + colg]     = y0;
                out[((size_t)frow * TT + t) * HH + colg + 1] = y1;
                float* hn = out + (size_t)BB * TT * HH;
                hn[(size_t)(frow * 2 + 1) * HH + colg]     = y0;
                hn[(size_t)(frow * 2 + 1) * HH + colg + 1] = y1;
                u32 vh = ((const u32*)g_A0[t & 1][0])[wadd];
                u32 vl = ((const u32*)g_A0[t & 1][1])[wadd];
                hn[(size_t)(frow * 2) * HH + colg]     = bflo(vh) + bflo(vl);
                hn[(size_t)(frow * 2) * HH + colg + 1] = bfhi(vh) + bfhi(vl);
            }
        }
    }
}

/* ------------------------------------------------------------------ */
extern "C" void kernel_launch(void* const* d_in, const int* in_sizes, int n_in,
                              void* d_out, int out_size)
{
    const float* x  = (const float*)d_in[0];
    const float* h0 = (const float*)d_in[1];
    const float* Wi = (const float*)d_in[2];
    const float* bi = (const float*)d_in[3];
    const float* Wh = (const float*)d_in[4];
    const float* bh = (const float*)d_in[5];
    float* out = (float*)d_out;

    dim3 g2(16, 256);
    pre_gemm<<<g2, 256>>>(x, Wi, bi);

    size_t smem = 24576 * sizeof(u32) + 4160 * sizeof(float);   /* ~112.6 KB */
    cudaFuncSetAttribute(rnn_persist, cudaFuncAttributeMaxDynamicSharedMemorySize, (int)smem);
    rnn_persist<<<NBLK, NTH, smem>>>(h0, Wi, bi, Wh, bh, out);
}

// round 13
// speedup vs baseline: 2.8052x; 1.2063x over previous
#include <cuda_runtime.h>
#include <cuda_bf16.h>
#include <math.h>

#define BB   128
#define TT   256
#define HH   1024
#define KG   256
#define NBLK 128
#define NJ   8
#define NTH  512

typedef unsigned long long u64;
typedef unsigned int u32;

/* Scratch (static device globals; no runtime allocation). */
__device__ float4 g_pre0[(size_t)TT * KG * BB];   /* [t][j4][b] fp32 */
__device__ uint4  g_xfrag[2][(size_t)TT * 16384]; /* [hi/lo][t][mt*64+kt][lane] A-frags of x */
__device__ uint2  g_wfrag[2][64 * 128 * 32];      /* [hi/lo][(kt*128+jt)*32+lane] B-frags of Wi0 */
__device__ uint4  g_A0[2][2][16384];              /* [parity][hi/lo] layer-0 h */
__device__ uint4  g_A1[2][2][16384];              /* [parity][hi/lo] layer-1 h */
__device__ u32    g_flags[NBLK * 64];

/* ---------------- helpers ---------------- */
__device__ __forceinline__ uint4 ldcg4(const uint4* p) {
    uint4 v;
    asm("ld.global.cg.v4.u32 {%0,%1,%2,%3}, [%4];"
        : "=r"(v.x), "=r"(v.y), "=r"(v.z), "=r"(v.w) : "l"(p));
    return v;
}
__device__ __forceinline__ uint2 ldcg2u(const uint2* p) {
    uint2 v;
    asm("ld.global.cg.v2.u32 {%0,%1}, [%2];" : "=r"(v.x), "=r"(v.y) : "l"(p));
    return v;
}
__device__ __forceinline__ void mma16816(float* d, uint4 a, uint2 b) {
    asm("mma.sync.aligned.m16n8k16.row.col.f32.bf16.bf16.f32 "
        "{%0,%1,%2,%3}, {%4,%5,%6,%7}, {%8,%9}, {%0,%1,%2,%3};"
        : "+f"(d[0]), "+f"(d[1]), "+f"(d[2]), "+f"(d[3])
        : "r"(a.x), "r"(a.y), "r"(a.z), "r"(a.w), "r"(b.x), "r"(b.y));
}
__device__ __forceinline__ u32 bfpack(float x, float y) {
    unsigned short lx = __bfloat16_as_ushort(__float2bfloat16(x));
    unsigned short ly = __bfloat16_as_ushort(__float2bfloat16(y));
    return (u32)lx | ((u32)ly << 16);
}
__device__ __forceinline__ float bfr(float x) { return __bfloat162float(__float2bfloat16(x)); }
__device__ __forceinline__ float bflo(u32 v) { return __bfloat162float(__ushort_as_bfloat16((unsigned short)(v & 0xffff))); }
__device__ __forceinline__ float bfhi(u32 v) { return __bfloat162float(__ushort_as_bfloat16((unsigned short)(v >> 16))); }

/* ------------------------------------------------------------------ */
/* Kernel 0: x -> split-bf16 A-fragment planes. grid (256 t, 8 mt).    */
/* Also resets barrier flags (graph replay safe).                      */
/* ------------------------------------------------------------------ */
__global__ __launch_bounds__(256) void x_convert(const float* __restrict__ x)
{
    if (blockIdx.x == 0 && blockIdx.y == 0 && threadIdx.x < NBLK)
        g_flags[threadIdx.x * 64] = 0u;

    const int t    = blockIdx.x;
    const int mt   = blockIdx.y;
    const int th   = threadIdx.x;
    const int w    = th >> 5;
    const int lane = th & 31;

    const int r  = mt * 16 + (lane >> 2);
    const float* b0 = x + ((size_t)r * TT + t) * HH;
    const float* b1 = x + ((size_t)(r + 8) * TT + t) * HH;

    for (int kt = w; kt < 64; kt += 8) {
        int k0 = kt * 16 + (lane & 3) * 2;
        float2 v00 = *(const float2*)(b0 + k0);
        float2 v10 = *(const float2*)(b1 + k0);
        float2 v01 = *(const float2*)(b0 + k0 + 8);
        float2 v11 = *(const float2*)(b1 + k0 + 8);
        uint4 hi, lo;
        hi.x = bfpack(v00.x, v00.y);
        hi.y = bfpack(v10.x, v10.y);
        hi.z = bfpack(v01.x, v01.y);
        hi.w = bfpack(v11.x, v11.y);
        lo.x = bfpack(v00.x - bfr(v00.x), v00.y - bfr(v00.y));
        lo.y = bfpack(v10.x - bfr(v10.x), v10.y - bfr(v10.y));
        lo.z = bfpack(v01.x - bfr(v01.x), v01.y - bfr(v01.y));
        lo.w = bfpack(v11.x - bfr(v11.x), v11.y - bfr(v11.y));
        size_t fo = (size_t)t * 16384 + (mt * 64 + kt) * 32 + lane;
        g_xfrag[0][fo] = hi;
        g_xfrag[1][fo] = lo;
    }
}

/* ------------------------------------------------------------------ */
/* Kernel 0b: Wi0 -> split-bf16 B-fragment planes. grid 64 (kt).       */
/* ------------------------------------------------------------------ */
__global__ __launch_bounds__(256) void w_convert(const float* __restrict__ Wi)
{
    const int kt = blockIdx.x;
    for (int idx = threadIdx.x; idx < 128 * 32; idx += 256) {
        int jt = idx >> 5, l = idx & 31;
        int n  = jt * 8 + (l >> 2);
        int k0 = kt * 16 + (l & 3) * 2;
        float w00 = Wi[(size_t)k0 * HH + n];
        float w01 = Wi[(size_t)(k0 + 1) * HH + n];
        float w10 = Wi[(size_t)(k0 + 8) * HH + n];
        float w11 = Wi[(size_t)(k0 + 9) * HH + n];
        uint2 hi, lo;
        hi.x = bfpack(w00, w01);
        hi.y = bfpack(w10, w11);
        lo.x = bfpack(w00 - bfr(w00), w01 - bfr(w01));
        lo.y = bfpack(w10 - bfr(w10), w11 - bfr(w11));
        size_t fo = ((size_t)kt * 128 + jt) * 32 + l;
        g_wfrag[0][fo] = hi;
        g_wfrag[1][fo] = lo;
    }
}

/* ------------------------------------------------------------------ */
/* Kernel 1: pre0 = x @ Wi0 + bi0 on tensor cores (split-bf16).        */
/* grid (16 jb, 256 t), 512 thr; warp = (mt 0..7, nh 0..1);            */
/* warp tile = 16 rows x 32 cols (4 n-tiles), K = 64 k-tiles.          */
/* ------------------------------------------------------------------ */
__global__ __launch_bounds__(NTH) void pre_mma(const float* __restrict__ bi)
{
    const int jb   = blockIdx.x;
    const int t    = blockIdx.y;
    const int wid  = threadIdx.x >> 5;
    const int lane = threadIdx.x & 31;
    const int mt   = wid & 7;
    const int nh   = wid >> 3;
    const int jt0  = jb * 8 + nh * 4;

    const uint4* pXh = g_xfrag[0] + (size_t)t * 16384 + (size_t)(mt * 64) * 32 + lane;
    const uint4* pXl = g_xfrag[1] + (size_t)t * 16384 + (size_t)(mt * 64) * 32 + lane;
    const uint2* pWh = g_wfrag[0] + (size_t)jt0 * 32 + lane;
    const uint2* pWl = g_wfrag[1] + (size_t)jt0 * 32 + lane;

    float acc[4][4];
#pragma unroll
    for (int nt = 0; nt < 4; ++nt)
#pragma unroll
        for (int r = 0; r < 4; ++r) acc[nt][r] = 0.0f;

    uint4 Xh0, Xl0, Xh1, Xl1;
    uint2 Wh0[4], Wl0[4], Wh1[4], Wl1[4];

    Xh0 = ldcg4(pXh); Xl0 = ldcg4(pXl);
#pragma unroll
    for (int nt = 0; nt < 4; ++nt) {
        Wh0[nt] = ldcg2u(pWh + nt * 32);
        Wl0[nt] = ldcg2u(pWl + nt * 32);
    }

#pragma unroll 1
    for (int kt = 0; kt < 64; kt += 2) {
        /* prefetch kt+1 */
        if (kt + 1 < 64) {
            Xh1 = ldcg4(pXh + (kt + 1) * 32);
            Xl1 = ldcg4(pXl + (kt + 1) * 32);
#pragma unroll
            for (int nt = 0; nt < 4; ++nt) {
                Wh1[nt] = ldcg2u(pWh + ((kt + 1) * 128 + nt) * 32);
                Wl1[nt] = ldcg2u(pWl + ((kt + 1) * 128 + nt) * 32);
            }
        }
#pragma unroll
        for (int nt = 0; nt < 4; ++nt) {
            mma16816(acc[nt], Xh0, Wh0[nt]);
            mma16816(acc[nt], Xh0, Wl0[nt]);
            mma16816(acc[nt], Xl0, Wh0[nt]);
        }
        /* prefetch kt+2 */
        if (kt + 2 < 64) {
            Xh0 = ldcg4(pXh + (kt + 2) * 32);
            Xl0 = ldcg4(pXl + (kt + 2) * 32);
#pragma unroll
            for (int nt = 0; nt < 4; ++nt) {
                Wh0[nt] = ldcg2u(pWh + ((kt + 2) * 128 + nt) * 32);
                Wl0[nt] = ldcg2u(pWl + ((kt + 2) * 128 + nt) * 32);
            }
        }
#pragma unroll
        for (int nt = 0; nt < 4; ++nt) {
            mma16816(acc[nt], Xh1, Wh1[nt]);
            mma16816(acc[nt], Xh1, Wl1[nt]);
            mma16816(acc[nt], Xl1, Wh1[nt]);
        }
    }

    /* Epilogue: D frag -> g_pre0 ([t][jg4][b] float4 layout) + bias. */
    const int r = mt * 16 + (lane >> 2);
    float* preF = (float*)g_pre0;
#pragma unroll
    for (int nt = 0; nt < 4; ++nt) {
        int col = (jt0 + nt) * 8 + (lane & 3) * 2;
        float b0v = __ldg(&bi[col]);
        float b1v = __ldg(&bi[col + 1]);
        int jg4 = col >> 2, cl = col & 3;
        size_t base = ((size_t)t * KG + jg4) * BB;
        float2 v0 = make_float2(acc[nt][0] + b0v, acc[nt][1] + b1v);
        float2 v1 = make_float2(acc[nt][2] + b0v, acc[nt][3] + b1v);
        *(float2*)(preF + (base + r) * 4 + cl)     = v0;
        *(float2*)(preF + (base + r + 8) * 4 + cl) = v1;
    }
}

/* ---------------- distributed grid barrier ---------------- */
__device__ __forceinline__ void grid_arrive(int cta, int th, u32 ph)
{
    __syncthreads();
    if (th == 0) {
        asm volatile("st.release.gpu.global.u32 [%0], %1;"
                     :: "l"(&g_flags[cta * 64]), "r"(ph) : "memory");
    }
}
__device__ __forceinline__ void grid_wait(int th, u32 ph)
{
    if (th < NBLK) {
        u32 v;
        do {
            asm volatile("ld.acquire.gpu.global.u32 %0, [%1];"
                         : "=r"(v) : "l"(&g_flags[th * 64]) : "memory");
        } while (v < ph);
    }
    __syncthreads();
}

/* MMA compute for one k-tile: 9 mma, 6 accumulator chains (R12). */
#define COMPUTE_KT(a0h, a0l, a1h, a1l, KT)                                   \
    {                                                                        \
        int kt_ = (KT);                                                      \
        uint2 w0h = sB2[0 * 2048 + kt_ * 32 + lane];                         \
        uint2 w0l = sB2[1 * 2048 + kt_ * 32 + lane];                         \
        uint2 w1h = sB2[2 * 2048 + kt_ * 32 + lane];                         \
        uint2 w1l = sB2[3 * 2048 + kt_ * 32 + lane];                         \
        uint2 w2h = sB2[4 * 2048 + kt_ * 32 + lane];                         \
        uint2 w2l = sB2[5 * 2048 + kt_ * 32 + lane];                         \
        mma16816(acc1a,  a0h, w0h);                                          \
        mma16816(acc1b,  a1h, w1h);                                          \
        mma16816(acc0,   a0h, w2h);                                          \
        mma16816(acc1a2, a0h, w0l);                                          \
        mma16816(acc1b2, a1h, w1l);                                          \
        mma16816(acc0b,  a0h, w2l);                                          \
        mma16816(acc1a2, a0l, w0h);                                          \
        mma16816(acc1b2, a1l, w1h);                                          \
        mma16816(acc0b,  a0l, w2h);                                          \
    }

#define LOADA(a0h, a0l, a1h, a1l, KT)                                        \
    {                                                                        \
        int fo_ = (mt * 64 + (KT)) * 32 + lane;                              \
        a0h = ldcg4(pA0h + fo_);  a0l = ldcg4(pA0l + fo_);                   \
        a1h = ldcg4(pA1h + fo_);  a1l = ldcg4(pA1l + fo_);                   \
    }

/* ------------------------------------------------------------------ */
/* Kernel 2: persistent RNN on tensor cores (unchanged from R12).      */
/* ------------------------------------------------------------------ */
__global__ __launch_bounds__(NTH, 1) void rnn_persist(const float* __restrict__ h0,
                                                      const float* __restrict__ Wi,
                                                      const float* __restrict__ bi,
                                                      const float* __restrict__ Wh,
                                                      const float* __restrict__ bh,
                                                      float* __restrict__ out)
{
    extern __shared__ u32 smemU[];
    u32*   sBu = smemU;
    const uint2* sB2 = (const uint2*)smemU;
    float* sr  = (float*)(smemU + 24576);
    float* sr0 = sr + 2080;

    const int cta  = blockIdx.x;
    const int th   = threadIdx.x;
    const int wid  = th >> 5;
    const int lane = th & 31;
    const int mt   = wid & 7;
    const int kh   = wid >> 3;
    const int j0   = cta * NJ;

    const int frow = th >> 2;
    const int c0   = (th & 3) * 2;
    const int fjg4 = (j0 + c0) >> 2;
    const int fcl  = c0 & 3;
    const int colg = j0 + c0;
    const int wmt  = frow >> 4, wq = frow & 7, wrsel = (frow >> 3) & 1;
    const int wkt  = colg >> 4, wkb = (colg & 7) >> 1, wkhigh = (colg >> 3) & 1;
    const int wadd = (((wmt * 64 + wkt) * 32) + wq * 4 + wkb) * 4 + wrsel + 2 * wkhigh;

    const float* Wi1g = Wi + (size_t)HH * HH;
    const float* Wh1g = Wh + (size_t)HH * HH;

    for (int idx = th; idx < 24576; idx += NTH) {
        int ms = idx >> 12;
        int m  = ms >> 1, s = ms & 1;
        int rem = idx & 4095;
        int kt = rem >> 6, lr = rem & 63;
        int l  = lr >> 1, r = lr & 1;
        int n  = l >> 2;
        int k0 = kt * 16 + (l & 3) * 2 + r * 8;
        const float* M = (m == 0) ? Wi1g : (m == 1) ? Wh1g : Wh;
        float w0 = M[(size_t)k0 * HH + j0 + n];
        float w1 = M[(size_t)(k0 + 1) * HH + j0 + n];
        if (s == 1) { w0 = w0 - bfr(w0); w1 = w1 - bfr(w1); }
        sBu[idx] = bfpack(w0, w1);
    }

    const float bs1_0 = __ldg(&bi[HH + colg])     + __ldg(&bh[HH + colg]);
    const float bs1_1 = __ldg(&bi[HH + colg + 1]) + __ldg(&bh[HH + colg + 1]);
    const float b0r_0 = __ldg(&bh[colg]);
    const float b0r_1 = __ldg(&bh[colg + 1]);

    {
        float y0 = h0[HH + colg], y1 = h0[HH + colg + 1];
        ((u32*)g_A1[1][0])[wadd] = bfpack(y0, y1);
        ((u32*)g_A1[1][1])[wadd] = bfpack(y0 - bfr(y0), y1 - bfr(y1));
    }
    __syncthreads();

    {
        int icol = th >> 6, ipart = th & 63;
        float dot = 0.0f;
        for (int e = 0; e < 16; ++e) {
            int k = ipart * 16 + e;
            int l = icol * 4 + ((k & 7) >> 1);
            int r = (k >> 3) & 1;
            u32 vh = sBu[4 * 4096 + ipart * 64 + l * 2 + r];
            u32 vl = sBu[5 * 4096 + ipart * 64 + l * 2 + r];
            float w = ((k & 1) ? bfhi(vh) : bflo(vh)) + ((k & 1) ? bfhi(vl) : bflo(vl));
            dot = fmaf(w, h0[k], dot);
        }
        sr[icol * 64 + ipart] = dot;
    }
    __syncthreads();
    {
        float dv0 = 0.0f, dv1 = 0.0f;
#pragma unroll 8
        for (int p = 0; p < 64; ++p) {
            dv0 += sr[c0 * 64 + p];
            dv1 += sr[(c0 + 1) * 64 + p];
        }
        const float* preF = (const float*)g_pre0;
        float p0v = preF[((size_t)fjg4 * BB + frow) * 4 + fcl];
        float p1v = preF[((size_t)fjg4 * BB + frow) * 4 + fcl + 1];
        float y0 = tanhf(p0v + dv0 + b0r_0);
        float y1 = tanhf(p1v + dv1 + b0r_1);
        ((u32*)g_A0[0][0])[wadd] = bfpack(y0, y1);
        ((u32*)g_A0[0][1])[wadd] = bfpack(y0 - bfr(y0), y1 - bfr(y1));
    }

    u32 ph = 1;
    grid_arrive(cta, th, ph);
    grid_wait(th, ph);
    ++ph;

    const int rrow = mt * 16 + (lane >> 2);
    const int ccol = (lane & 3) * 2;

    for (int t = 0; t < TT; ++t) {
        const uint4* pA0h = g_A0[t & 1][0];
        const uint4* pA0l = g_A0[t & 1][1];
        const uint4* pA1h = g_A1[(t + 1) & 1][0];
        const uint4* pA1l = g_A1[(t + 1) & 1][1];

        float2 pn = make_float2(0.0f, 0.0f);
        if (t < TT - 1) {
            const float* pp = (const float*)g_pre0 +
                ((size_t)((size_t)(t + 1) * KG + fjg4) * BB + frow) * 4 + fcl;
            asm("ld.global.cg.v2.f32 {%0,%1}, [%2];" : "=f"(pn.x), "=f"(pn.y) : "l"(pp));
        }

        float acc1a[4]  = {0, 0, 0, 0};
        float acc1a2[4] = {0, 0, 0, 0};
        float acc1b[4]  = {0, 0, 0, 0};
        float acc1b2[4] = {0, 0, 0, 0};
        float acc0[4]   = {0, 0, 0, 0};
        float acc0b[4]  = {0, 0, 0, 0};

        {
            const int ktb = kh * 32;
            uint4 Xa0h, Xa0l, Xa1h, Xa1l, Ya0h, Ya0l, Ya1h, Ya1l;
            LOADA(Xa0h, Xa0l, Xa1h, Xa1l, ktb);
#pragma unroll 1
            for (int i = 0; i < 32; i += 2) {
                LOADA(Ya0h, Ya0l, Ya1h, Ya1l, ktb + i + 1);
                COMPUTE_KT(Xa0h, Xa0l, Xa1h, Xa1l, ktb + i);
                if (i + 2 < 32) { LOADA(Xa0h, Xa0l, Xa1h, Xa1l, ktb + i + 2); }
                COMPUTE_KT(Ya0h, Ya0l, Ya1h, Ya1l, ktb + i + 1);
            }
        }

        {
            int b1 = (kh * 8 + ccol) * 130;
            sr [b1 + rrow]           = acc1a[0] + acc1a2[0] + acc1b[0] + acc1b2[0];
            sr [b1 + 130 + rrow]     = acc1a[1] + acc1a2[1] + acc1b[1] + acc1b2[1];
            sr [b1 + rrow + 8]       = acc1a[2] + acc1a2[2] + acc1b[2] + acc1b2[2];
            sr [b1 + 130 + rrow + 8] = acc1a[3] + acc1a2[3] + acc1b[3] + acc1b2[3];
            sr0[b1 + rrow]           = acc0[0] + acc0b[0];
            sr0[b1 + 130 + rrow]     = acc0[1] + acc0b[1];
            sr0[b1 + rrow + 8]       = acc0[2] + acc0b[2];
            sr0[b1 + 130 + rrow + 8] = acc0[3] + acc0b[3];
        }
        __syncthreads();

        {
            float s1_0 = sr[(0 * 8 + c0) * 130 + frow]       + sr[(1 * 8 + c0) * 130 + frow];
            float s1_1 = sr[(0 * 8 + c0 + 1) * 130 + frow]   + sr[(1 * 8 + c0 + 1) * 130 + frow];
            float y0 = tanhf(s1_0 + bs1_0);
            float y1 = tanhf(s1_1 + bs1_1);

            ((u32*)g_A1[t & 1][0])[wadd] = bfpack(y0, y1);
            ((u32*)g_A1[t & 1][1])[wadd] = bfpack(y0 - bfr(y0), y1 - bfr(y1));

            if (t < TT - 1) {
                float s0_0 = sr0[(0 * 8 + c0) * 130 + frow]     + sr0[(1 * 8 + c0) * 130 + frow];
                float s0_1 = sr0[(0 * 8 + c0 + 1) * 130 + frow] + sr0[(1 * 8 + c0 + 1) * 130 + frow];
                float z0 = tanhf(s0_0 + pn.x + b0r_0);
                float z1 = tanhf(s0_1 + pn.y + b0r_1);
                ((u32*)g_A0[(t + 1) & 1][0])[wadd] = bfpack(z0, z1);
                ((u32*)g_A0[(t + 1) & 1][1])[wadd] = bfpack(z0 - bfr(z0), z1 - bfr(z1));

                grid_arrive(cta, th, ph);
                out[((size_t)frow * TT + t) * HH + colg]     = y0;
                out[((size_t)frow * TT + t) * HH + colg + 1] = y1;
                grid_wait(th, ph);
                ++ph;
            } else {
                out[((size_t)frow * TT + t) * HH + colg]     = y0;
                out[((size_t)frow * TT + t) * HH + colg + 1] = y1;
                float* hn = out + (size_t)BB * TT * HH;
                hn[(size_t)(frow * 2 + 1) * HH + colg]     = y0;
                hn[(size_t)(frow * 2 + 1) * HH + colg + 1] = y1;
                u32 vh = ((const u32*)g_A0[t & 1][0])[wadd];
                u32 vl = ((const u32*)g_A0[t & 1][1])[wadd];
                hn[(size_t)(frow * 2) * HH + colg]     = bflo(vh) + bflo(vl);
                hn[(size_t)(frow * 2) * HH + colg + 1] = bfhi(vh) + bfhi(vl);
            }
        }
    }
}

/* ------------------------------------------------------------------ */
extern "C" void kernel_launch(void* const* d_in, const int* in_sizes, int n_in,
                              void* d_out, int out_size)
{
    const float* x  = (const float*)d_in[0];
    const float* h0 = (const float*)d_in[1];
    const float* Wi = (const float*)d_in[2];
    const float* bi = (const float*)d_in[3];
    const float* Wh = (const float*)d_in[4];
    const float* bh = (const float*)d_in[5];
    float* out = (float*)d_out;

    x_convert<<<dim3(256, 8), 256>>>(x);
    w_convert<<<64, 256>>>(Wi);
    pre_mma<<<dim3(16, 256), NTH>>>(bi);

    size_t smem = 24576 * sizeof(u32) + 4160 * sizeof(float);   /* ~112.6 KB */
    cudaFuncSetAttribute(rnn_persist, cudaFuncAttributeMaxDynamicSharedMemorySize, (int)smem);
    rnn_persist<<<NBLK, NTH, smem>>>(h0, Wi, bi, Wh, bh, out);
}

// round 14
// speedup vs baseline: 3.1685x; 1.1295x over previous
#include <cuda_runtime.h>
#include <cuda_bf16.h>
#include <math.h>

#define BB   128
#define TT   256
#define HH   1024
#define KG   256
#define NBLK 128
#define NJ   8
#define NTH  512

typedef unsigned long long u64;
typedef unsigned int u32;

/* Scratch (static device globals; no runtime allocation). */
__device__ float4 g_pre0[(size_t)TT * KG * BB];   /* [t][j4][b] fp32 */
__device__ uint4  g_xfrag[2][(size_t)TT * 16384]; /* [hi/lo][t][mt*64+kt][lane] A-frags of x */
__device__ uint2  g_wfrag[2][64 * 128 * 32];      /* [hi/lo][(kt*128+jt)*32+lane] B-frags of Wi0 */
__device__ uint4  g_A0[2][2][16384];              /* [parity][hi/lo] layer-0 h */
__device__ uint4  g_A1[2][2][16384];              /* [parity][hi/lo] layer-1 h */
__device__ u32    g_flags[NBLK * 64];

/* ---------------- helpers ---------------- */
__device__ __forceinline__ uint4 ldcg4(const uint4* p) {
    uint4 v;
    asm("ld.global.cg.v4.u32 {%0,%1,%2,%3}, [%4];"
        : "=r"(v.x), "=r"(v.y), "=r"(v.z), "=r"(v.w) : "l"(p));
    return v;
}
__device__ __forceinline__ uint2 ldcg2u(const uint2* p) {
    uint2 v;
    asm("ld.global.cg.v2.u32 {%0,%1}, [%2];" : "=r"(v.x), "=r"(v.y) : "l"(p));
    return v;
}
__device__ __forceinline__ void mma16816(float* d, uint4 a, uint2 b) {
    asm("mma.sync.aligned.m16n8k16.row.col.f32.bf16.bf16.f32 "
        "{%0,%1,%2,%3}, {%4,%5,%6,%7}, {%8,%9}, {%0,%1,%2,%3};"
        : "+f"(d[0]), "+f"(d[1]), "+f"(d[2]), "+f"(d[3])
        : "r"(a.x), "r"(a.y), "r"(a.z), "r"(a.w), "r"(b.x), "r"(b.y));
}
__device__ __forceinline__ u32 bfpack(float x, float y) {
    unsigned short lx = __bfloat16_as_ushort(__float2bfloat16(x));
    unsigned short ly = __bfloat16_as_ushort(__float2bfloat16(y));
    return (u32)lx | ((u32)ly << 16);
}
__device__ __forceinline__ float bfr(float x) { return __bfloat162float(__float2bfloat16(x)); }
__device__ __forceinline__ float bflo(u32 v) { return __bfloat162float(__ushort_as_bfloat16((unsigned short)(v & 0xffff))); }
__device__ __forceinline__ float bfhi(u32 v) { return __bfloat162float(__ushort_as_bfloat16((unsigned short)(v >> 16))); }

/* ------------------------------------------------------------------ */
/* Kernel 0: x -> split-bf16 A-fragment planes. grid (256 t, 8 mt).    */
/* ------------------------------------------------------------------ */
__global__ __launch_bounds__(256) void x_convert(const float* __restrict__ x)
{
    if (blockIdx.x == 0 && blockIdx.y == 0 && threadIdx.x < NBLK)
        g_flags[threadIdx.x * 64] = 0u;

    const int t    = blockIdx.x;
    const int mt   = blockIdx.y;
    const int th   = threadIdx.x;
    const int w    = th >> 5;
    const int lane = th & 31;

    const int r  = mt * 16 + (lane >> 2);
    const float* b0 = x + ((size_t)r * TT + t) * HH;
    const float* b1 = x + ((size_t)(r + 8) * TT + t) * HH;

    for (int kt = w; kt < 64; kt += 8) {
        int k0 = kt * 16 + (lane & 3) * 2;
        float2 v00 = *(const float2*)(b0 + k0);
        float2 v10 = *(const float2*)(b1 + k0);
        float2 v01 = *(const float2*)(b0 + k0 + 8);
        float2 v11 = *(const float2*)(b1 + k0 + 8);
        uint4 hi, lo;
        hi.x = bfpack(v00.x, v00.y);
        hi.y = bfpack(v10.x, v10.y);
        hi.z = bfpack(v01.x, v01.y);
        hi.w = bfpack(v11.x, v11.y);
        lo.x = bfpack(v00.x - bfr(v00.x), v00.y - bfr(v00.y));
        lo.y = bfpack(v10.x - bfr(v10.x), v10.y - bfr(v10.y));
        lo.z = bfpack(v01.x - bfr(v01.x), v01.y - bfr(v01.y));
        lo.w = bfpack(v11.x - bfr(v11.x), v11.y - bfr(v11.y));
        size_t fo = (size_t)t * 16384 + (mt * 64 + kt) * 32 + lane;
        g_xfrag[0][fo] = hi;
        g_xfrag[1][fo] = lo;
    }
}

/* ------------------------------------------------------------------ */
/* Kernel 0b: Wi0 -> split-bf16 B-fragment planes. grid 64 (kt).       */
/* ------------------------------------------------------------------ */
__global__ __launch_bounds__(256) void w_convert(const float* __restrict__ Wi)
{
    const int kt = blockIdx.x;
    for (int idx = threadIdx.x; idx < 128 * 32; idx += 256) {
        int jt = idx >> 5, l = idx & 31;
        int n  = jt * 8 + (l >> 2);
        int k0 = kt * 16 + (l & 3) * 2;
        float w00 = Wi[(size_t)k0 * HH + n];
        float w01 = Wi[(size_t)(k0 + 1) * HH + n];
        float w10 = Wi[(size_t)(k0 + 8) * HH + n];
        float w11 = Wi[(size_t)(k0 + 9) * HH + n];
        uint2 hi, lo;
        hi.x = bfpack(w00, w01);
        hi.y = bfpack(w10, w11);
        lo.x = bfpack(w00 - bfr(w00), w01 - bfr(w01));
        lo.y = bfpack(w10 - bfr(w10), w11 - bfr(w11));
        size_t fo = ((size_t)kt * 128 + jt) * 32 + l;
        g_wfrag[0][fo] = hi;
        g_wfrag[1][fo] = lo;
    }
}

/* ------------------------------------------------------------------ */
/* Kernel 1: pre0 = x @ Wi0 + bi0 on tensor cores (unchanged R13).     */
/* ------------------------------------------------------------------ */
__global__ __launch_bounds__(NTH) void pre_mma(const float* __restrict__ bi)
{
    const int jb   = blockIdx.x;
    const int t    = blockIdx.y;
    const int wid  = threadIdx.x >> 5;
    const int lane = threadIdx.x & 31;
    const int mt   = wid & 7;
    const int nh   = wid >> 3;
    const int jt0  = jb * 8 + nh * 4;

    const uint4* pXh = g_xfrag[0] + (size_t)t * 16384 + (size_t)(mt * 64) * 32 + lane;
    const uint4* pXl = g_xfrag[1] + (size_t)t * 16384 + (size_t)(mt * 64) * 32 + lane;
    const uint2* pWh = g_wfrag[0] + (size_t)jt0 * 32 + lane;
    const uint2* pWl = g_wfrag[1] + (size_t)jt0 * 32 + lane;

    float acc[4][4];
#pragma unroll
    for (int nt = 0; nt < 4; ++nt)
#pragma unroll
        for (int r = 0; r < 4; ++r) acc[nt][r] = 0.0f;

    uint4 Xh0, Xl0, Xh1, Xl1;
    uint2 Wh0[4], Wl0[4], Wh1[4], Wl1[4];

    Xh0 = ldcg4(pXh); Xl0 = ldcg4(pXl);
#pragma unroll
    for (int nt = 0; nt < 4; ++nt) {
        Wh0[nt] = ldcg2u(pWh + nt * 32);
        Wl0[nt] = ldcg2u(pWl + nt * 32);
    }

#pragma unroll 1
    for (int kt = 0; kt < 64; kt += 2) {
        if (kt + 1 < 64) {
            Xh1 = ldcg4(pXh + (kt + 1) * 32);
            Xl1 = ldcg4(pXl + (kt + 1) * 32);
#pragma unroll
            for (int nt = 0; nt < 4; ++nt) {
                Wh1[nt] = ldcg2u(pWh + ((kt + 1) * 128 + nt) * 32);
                Wl1[nt] = ldcg2u(pWl + ((kt + 1) * 128 + nt) * 32);
            }
        }
#pragma unroll
        for (int nt = 0; nt < 4; ++nt) {
            mma16816(acc[nt], Xh0, Wh0[nt]);
            mma16816(acc[nt], Xh0, Wl0[nt]);
            mma16816(acc[nt], Xl0, Wh0[nt]);
        }
        if (kt + 2 < 64) {
            Xh0 = ldcg4(pXh + (kt + 2) * 32);
            Xl0 = ldcg4(pXl + (kt + 2) * 32);
#pragma unroll
            for (int nt = 0; nt < 4; ++nt) {
                Wh0[nt] = ldcg2u(pWh + ((kt + 2) * 128 + nt) * 32);
                Wl0[nt] = ldcg2u(pWl + ((kt + 2) * 128 + nt) * 32);
            }
        }
#pragma unroll
        for (int nt = 0; nt < 4; ++nt) {
            mma16816(acc[nt], Xh1, Wh1[nt]);
            mma16816(acc[nt], Xh1, Wl1[nt]);
            mma16816(acc[nt], Xl1, Wh1[nt]);
        }
    }

    const int r = mt * 16 + (lane >> 2);
    float* preF = (float*)g_pre0;
#pragma unroll
    for (int nt = 0; nt < 4; ++nt) {
        int col = (jt0 + nt) * 8 + (lane & 3) * 2;
        float b0v = __ldg(&bi[col]);
        float b1v = __ldg(&bi[col + 1]);
        int jg4 = col >> 2, cl = col & 3;
        size_t base = ((size_t)t * KG + jg4) * BB;
        float2 v0 = make_float2(acc[nt][0] + b0v, acc[nt][1] + b1v);
        float2 v1 = make_float2(acc[nt][2] + b0v, acc[nt][3] + b1v);
        *(float2*)(preF + (base + r) * 4 + cl)     = v0;
        *(float2*)(preF + (base + r + 8) * 4 + cl) = v1;
    }
}

/* ---------------- distributed grid barrier ---------------- */
__device__ __forceinline__ void grid_arrive(int cta, int th, u32 ph)
{
    __syncthreads();
    if (th == 0) {
        asm volatile("st.release.gpu.global.u32 [%0], %1;"
                     :: "l"(&g_flags[cta * 64]), "r"(ph) : "memory");
    }
}
__device__ __forceinline__ void grid_wait(int th, u32 ph)
{
    if (th < NBLK) {
        u32 v;
        do {
            asm volatile("ld.acquire.gpu.global.u32 %0, [%1];"
                         : "=r"(v) : "l"(&g_flags[th * 64]) : "memory");
        } while (v < ph);
    }
    __syncthreads();
}

/* Load A frags (4 planes) for m-tile MT at k-tile KT into stage R. */
#define LOADMT(R, MT, KT)                                                    \
    {                                                                        \
        int fo_ = ((MT) * 64 + (KT)) * 32 + lane;                            \
        R##h0 = ldcg4(pA0h + fo_);  R##l0 = ldcg4(pA0l + fo_);               \
        R##h1 = ldcg4(pA1h + fo_);  R##l1 = ldcg4(pA1l + fo_);               \
    }

/* Load shared weight frags for k-tile KT (reused by both m-tiles). */
#define LDW(KT)                                                              \
    {                                                                        \
        int kt_ = (KT);                                                      \
        w0h = sB2[0 * 2048 + kt_ * 32 + lane];                               \
        w0l = sB2[1 * 2048 + kt_ * 32 + lane];                               \
        w1h = sB2[2 * 2048 + kt_ * 32 + lane];                               \
        w1l = sB2[3 * 2048 + kt_ * 32 + lane];                               \
        w2h = sB2[4 * 2048 + kt_ * 32 + lane];                               \
        w2l = sB2[5 * 2048 + kt_ * 32 + lane];                               \
    }

/* 9 MMAs for one m-tile using the shared weight frags. */
#define COMPM(R, Q1, Q1X, Q0)                                                \
    mma16816(Q1,  R##h0, w0h);                                               \
    mma16816(Q1X, R##h0, w0l);                                               \
    mma16816(Q1X, R##l0, w0h);                                               \
    mma16816(Q1,  R##h1, w1h);                                               \
    mma16816(Q1X, R##h1, w1l);                                               \
    mma16816(Q1X, R##l1, w1h);                                               \
    mma16816(Q0,  R##h0, w2h);                                               \
    mma16816(Q0,  R##h0, w2l);                                               \
    mma16816(Q0,  R##l0, w2h);

/* ------------------------------------------------------------------ */
/* Kernel 2: persistent RNN on tensor cores, mt-paired warps.          */
/* 16 warps = 4 mt-pairs x 4 K-quarters; weight LDS halved.            */
/* ------------------------------------------------------------------ */
__global__ __launch_bounds__(NTH, 1) void rnn_persist(const float* __restrict__ h0,
                                                      const float* __restrict__ Wi,
                                                      const float* __restrict__ bi,
                                                      const float* __restrict__ Wh,
                                                      const float* __restrict__ bh,
                                                      float* __restrict__ out)
{
    extern __shared__ u32 smemU[];
    u32*   sBu = smemU;                       /* 24576 u32 = 96KB weight frags */
    const uint2* sB2 = (const uint2*)smemU;
    float* sr  = (float*)(smemU + 24576);     /* acc1 partials: [4kh][8col][130] */
    float* sr0 = sr + 4160;                   /* acc0 partials */

    const int cta  = blockIdx.x;
    const int th   = threadIdx.x;
    const int wid  = th >> 5;
    const int lane = th & 31;
    const int mtp  = wid & 3;          /* m-tile pair 0..3 */
    const int kh   = wid >> 2;         /* K quarter 0..3 */
    const int mt0g = mtp * 2;
    const int mt1g = mtp * 2 + 1;
    const int j0   = cta * NJ;

    const int frow = th >> 2;
    const int c0   = (th & 3) * 2;
    const int fjg4 = (j0 + c0) >> 2;
    const int fcl  = c0 & 3;
    const int colg = j0 + c0;
    const int wmt  = frow >> 4, wq = frow & 7, wrsel = (frow >> 3) & 1;
    const int wkt  = colg >> 4, wkb = (colg & 7) >> 1, wkhigh = (colg >> 3) & 1;
    const int wadd = (((wmt * 64 + wkt) * 32) + wq * 4 + wkb) * 4 + wrsel + 2 * wkhigh;

    const float* Wi1g = Wi + (size_t)HH * HH;
    const float* Wh1g = Wh + (size_t)HH * HH;

    /* one-time: pack weights into bf16 hi/lo MMA fragments (R11 layout). */
    for (int idx = th; idx < 24576; idx += NTH) {
        int ms = idx >> 12;
        int m  = ms >> 1, s = ms & 1;
        int rem = idx & 4095;
        int kt = rem >> 6, lr = rem & 63;
        int l  = lr >> 1, r = lr & 1;
        int n  = l >> 2;
        int k0 = kt * 16 + (l & 3) * 2 + r * 8;
        const float* M = (m == 0) ? Wi1g : (m == 1) ? Wh1g : Wh;
        float w0 = M[(size_t)k0 * HH + j0 + n];
        float w1 = M[(size_t)(k0 + 1) * HH + j0 + n];
        if (s == 1) { w0 = w0 - bfr(w0); w1 = w1 - bfr(w1); }
        sBu[idx] = bfpack(w0, w1);
    }

    const float bs1_0 = __ldg(&bi[HH + colg])     + __ldg(&bh[HH + colg]);
    const float bs1_1 = __ldg(&bi[HH + colg + 1]) + __ldg(&bh[HH + colg + 1]);
    const float b0r_0 = __ldg(&bh[colg]);
    const float b0r_1 = __ldg(&bh[colg + 1]);

    /* h1 init -> A1 planes parity 1. */
    {
        float y0 = h0[HH + colg], y1 = h0[HH + colg + 1];
        ((u32*)g_A1[1][0])[wadd] = bfpack(y0, y1);
        ((u32*)g_A1[1][1])[wadd] = bfpack(y0 - bfr(y0), y1 - bfr(y1));
    }
    __syncthreads();

    /* hn0[0] init: dot0[col] = h0_l0 @ Wh0 via split-bf16 frags. */
    {
        int icol = th >> 6, ipart = th & 63;
        float dot = 0.0f;
        for (int e = 0; e < 16; ++e) {
            int k = ipart * 16 + e;
            int l = icol * 4 + ((k & 7) >> 1);
            int r = (k >> 3) & 1;
            u32 vh = sBu[4 * 4096 + ipart * 64 + l * 2 + r];
            u32 vl = sBu[5 * 4096 + ipart * 64 + l * 2 + r];
            float w = ((k & 1) ? bfhi(vh) : bflo(vh)) + ((k & 1) ? bfhi(vl) : bflo(vl));
            dot = fmaf(w, h0[k], dot);
        }
        sr[icol * 64 + ipart] = dot;
    }
    __syncthreads();
    {
        float dv0 = 0.0f, dv1 = 0.0f;
#pragma unroll 8
        for (int p = 0; p < 64; ++p) {
            dv0 += sr[c0 * 64 + p];
            dv1 += sr[(c0 + 1) * 64 + p];
        }
        const float* preF = (const float*)g_pre0;
        float p0v = preF[((size_t)fjg4 * BB + frow) * 4 + fcl];
        float p1v = preF[((size_t)fjg4 * BB + frow) * 4 + fcl + 1];
        float y0 = tanhf(p0v + dv0 + b0r_0);
        float y1 = tanhf(p1v + dv1 + b0r_1);
        ((u32*)g_A0[0][0])[wadd] = bfpack(y0, y1);
        ((u32*)g_A0[0][1])[wadd] = bfpack(y0 - bfr(y0), y1 - bfr(y1));
    }

    u32 ph = 1;
    grid_arrive(cta, th, ph);
    grid_wait(th, ph);
    ++ph;

    const int rrow0 = mt0g * 16 + (lane >> 2);
    const int rrow1 = mt1g * 16 + (lane >> 2);
    const int ccol  = (lane & 3) * 2;

    for (int t = 0; t < TT; ++t) {
        const uint4* pA0h = g_A0[t & 1][0];
        const uint4* pA0l = g_A0[t & 1][1];
        const uint4* pA1h = g_A1[(t + 1) & 1][0];
        const uint4* pA1l = g_A1[(t + 1) & 1][1];

        float2 pn = make_float2(0.0f, 0.0f);
        if (t < TT - 1) {
            const float* pp = (const float*)g_pre0 +
                ((size_t)((size_t)(t + 1) * KG + fjg4) * BB + frow) * 4 + fcl;
            asm("ld.global.cg.v2.f32 {%0,%1}, [%2];" : "=f"(pn.x), "=f"(pn.y) : "l"(pp));
        }

        float q1a[4]  = {0, 0, 0, 0}, q1xa[4] = {0, 0, 0, 0}, q0a[4] = {0, 0, 0, 0};
        float q1b[4]  = {0, 0, 0, 0}, q1xb[4] = {0, 0, 0, 0}, q0b[4] = {0, 0, 0, 0};

        {
            const int ktb = kh * 16;
            uint2 w0h, w0l, w1h, w1l, w2h, w2l;
            uint4 Ch0, Cl0, Ch1, Cl1;        /* stage C: mt0 */
            uint4 Dh0, Dl0, Dh1, Dl1;        /* stage D: mt1 */
            uint4 Eh0, El0, Eh1, El1;        /* stage E: mt0 next */
            uint4 Fh0, Fl0, Fh1, Fl1;        /* stage F: mt1 next */
            LOADMT(C, mt0g, ktb);
            LOADMT(D, mt1g, ktb);
#pragma unroll 1
            for (int kt = 0; kt < 16; kt += 2) {
                LDW(ktb + kt);
                LOADMT(E, mt0g, ktb + kt + 1);
                COMPM(C, q1a, q1xa, q0a);
                LOADMT(F, mt1g, ktb + kt + 1);
                COMPM(D, q1b, q1xb, q0b);
                LDW(ktb + kt + 1);
                if (kt + 2 < 16) { LOADMT(C, mt0g, ktb + kt + 2); }
                COMPM(E, q1a, q1xa, q0a);
                if (kt + 2 < 16) { LOADMT(D, mt1g, ktb + kt + 2); }
                COMPM(F, q1b, q1xb, q0b);
            }
        }

        /* write partials: [kh][col][row(130)] for acc1 and acc0. */
        {
            int b = (kh * 8 + ccol) * 130;
            sr [b + rrow0]           = q1a[0] + q1xa[0];
            sr [b + 130 + rrow0]     = q1a[1] + q1xa[1];
            sr [b + rrow0 + 8]       = q1a[2] + q1xa[2];
            sr [b + 130 + rrow0 + 8] = q1a[3] + q1xa[3];
            sr [b + rrow1]           = q1b[0] + q1xb[0];
            sr [b + 130 + rrow1]     = q1b[1] + q1xb[1];
            sr [b + rrow1 + 8]       = q1b[2] + q1xb[2];
            sr [b + 130 + rrow1 + 8] = q1b[3] + q1xb[3];
            sr0[b + rrow0]           = q0a[0];
            sr0[b + 130 + rrow0]     = q0a[1];
            sr0[b + rrow0 + 8]       = q0a[2];
            sr0[b + 130 + rrow0 + 8] = q0a[3];
            sr0[b + rrow1]           = q0b[0];
            sr0[b + 130 + rrow1]     = q0b[1];
            sr0[b + rrow1 + 8]       = q0b[2];
            sr0[b + 130 + rrow1 + 8] = q0b[3];
        }
        __syncthreads();

        /* final pass: (frow, c0..c0+1), 4-way kh reduction. */
        {
            float s1_0 = 0.0f, s1_1 = 0.0f;
#pragma unroll
            for (int k2 = 0; k2 < 4; ++k2) {
                s1_0 += sr[(k2 * 8 + c0) * 130 + frow];
                s1_1 += sr[(k2 * 8 + c0 + 1) * 130 + frow];
            }
            float y0 = tanhf(s1_0 + bs1_0);
            float y1 = tanhf(s1_1 + bs1_1);

            ((u32*)g_A1[t & 1][0])[wadd] = bfpack(y0, y1);
            ((u32*)g_A1[t & 1][1])[wadd] = bfpack(y0 - bfr(y0), y1 - bfr(y1));

            if (t < TT - 1) {
                float s0_0 = 0.0f, s0_1 = 0.0f;
#pragma unroll
                for (int k2 = 0; k2 < 4; ++k2) {
                    s0_0 += sr0[(k2 * 8 + c0) * 130 + frow];
                    s0_1 += sr0[(k2 * 8 + c0 + 1) * 130 + frow];
                }
                float z0 = tanhf(s0_0 + pn.x + b0r_0);
                float z1 = tanhf(s0_1 + pn.y + b0r_1);
                ((u32*)g_A0[(t + 1) & 1][0])[wadd] = bfpack(z0, z1);
                ((u32*)g_A0[(t + 1) & 1][1])[wadd] = bfpack(z0 - bfr(z0), z1 - bfr(z1));

                grid_arrive(cta, th, ph);
                out[((size_t)frow * TT + t) * HH + colg]     = y0;
                out[((size_t)frow * TT + t) * HH + colg + 1] = y1;
                grid_wait(th, ph);
                ++ph;
            } else {
                out[((size_t)frow * TT + t) * HH + colg]     = y0;
                out[((size_t)frow * TT + t) * HH + colg + 1] = y1;
                float* hn = out + (size_t)BB * TT * HH;
                hn[(size_t)(frow * 2 + 1) * HH + colg]     = y0;
                hn[(size_t)(frow * 2 + 1) * HH + colg + 1] = y1;
                u32 vh = ((const u32*)g_A0[t & 1][0])[wadd];
                u32 vl = ((const u32*)g_A0[t & 1][1])[wadd];
                hn[(size_t)(frow * 2) * HH + colg]     = bflo(vh) + bflo(vl);
                hn[(size_t)(frow * 2) * HH + colg + 1] = bfhi(vh) + bfhi(vl);
            }
        }
    }
}

/* ------------------------------------------------------------------ */
extern "C" void kernel_launch(void* const* d_in, const int* in_sizes, int n_in,
                              void* d_out, int out_size)
{
    const float* x  = (const float*)d_in[0];
    const float* h0 = (const float*)d_in[1];
    const float* Wi = (const float*)d_in[2];
    const float* bi = (const float*)d_in[3];
    const float* Wh = (const float*)d_in[4];
    const float* bh = (const float*)d_in[5];
    float* out = (float*)d_out;

    x_convert<<<dim3(256, 8), 256>>>(x);
    w_convert<<<64, 256>>>(Wi);
    pre_mma<<<dim3(16, 256), NTH>>>(bi);

    size_t smem = 24576 * sizeof(u32) + (2 * 4160 + 64) * sizeof(float);   /* ~129 KB */
    cudaFuncSetAttribute(rnn_persist, cudaFuncAttributeMaxDynamicSharedMemorySize, (int)smem);
    rnn_persist<<<NBLK, NTH, smem>>>(h0, Wi, bi, Wh, bh, out);
}